// round 14
// baseline (speedup 1.0000x reference)
#include <cuda_runtime.h>
#include <math.h>
#include <stdint.h>

#define DIM   512
#define NS    8
#define BATCH 128
#define NTOK  1024
#define HIDN  512
#define NROWS (BATCH*NTOK)   /* 131072 */
#define SROWS (BATCH*NS)     /* 1024   */
#define ATT_SCALE 0.04419417382415922f
#define LN_EPS 1e-5f
#define ATT_EPS 1e-8f

/* ---------------- scratch (device globals; no allocation) ---------------- */
__device__ float g_xn[(size_t)NROWS*DIM];
__device__ float g_WkT[DIM*DIM];
__device__ float g_WqT[DIM*DIM];
__device__ float g_WvT[DIM*DIM];
__device__ float g_Wp[DIM*DIM];          /* (Wq^T Wk) as W-operand layout */
__device__ float g_Wc[3*DIM*DIM];        /* Wih @ Wv */
__device__ float g_Wih_r[3*DIM*DIM];
__device__ float g_Whh_r[3*DIM*DIM];
__device__ float g_W1_r[HIDN*DIM];
__device__ float g_W2_r[DIM*HIDN];
__device__ float g_zero[DIM];
__device__ float g_v[DIM];
__device__ float g_u[DIM];
__device__ float g_c0[1];
__device__ float g_bc[3*DIM];
__device__ float g_s [SROWS*DIM];
__device__ float g_sr[SROWS*DIM];
__device__ float g_qk[SROWS*DIM];
__device__ float g_qbk[SROWS];
__device__ float g_paw[(size_t)BATCH*8*NS*DIM];   /* [b][blk][i][c], 16 MB */
__device__ float g_prs[BATCH*8*NS];
__device__ float g_awn[SROWS*DIM];
__device__ float g_xg[SROWS*3*DIM];
__device__ float g_hg[SROWS*3*DIM];
__device__ float g_hid[SROWS*HIDN];

/* ---------------- helpers ---------------- */
__device__ __forceinline__ float rtf32(float x) {
    uint32_t u; asm("cvt.rna.tf32.f32 %0, %1;" : "=r"(u) : "f"(x));
    return __uint_as_float(u);
}
__device__ __forceinline__ uint32_t s2u(const void* p) {
    uint32_t a;
    asm("{ .reg .u64 t; cvta.to.shared.u64 t, %1; cvt.u32.u64 %0, t; }" : "=r"(a) : "l"(p));
    return a;
}

#define CP16(dst, src) \
    asm volatile("cp.async.cg.shared.global [%0], [%1], 16;" :: "r"(dst), "l"(src))
#define CP_COMMIT() asm volatile("cp.async.commit_group;" ::: "memory")
#define CP_WAIT(n)  asm volatile("cp.async.wait_group %0;" :: "n"(n) : "memory")

#define MMA_TF32(d, a, b) \
    asm volatile("mma.sync.aligned.m16n8k8.row.col.f32.tf32.tf32.f32 " \
        "{%0,%1,%2,%3}, {%4,%5,%6,%7}, {%8,%9}, {%0,%1,%2,%3};" \
        : "+f"((d)[0]), "+f"((d)[1]), "+f"((d)[2]), "+f"((d)[3]) \
        : "r"(__float_as_uint((a)[0])), "r"(__float_as_uint((a)[1])), \
          "r"(__float_as_uint((a)[2])), "r"(__float_as_uint((a)[3])), \
          "r"(__float_as_uint((b)[0])), "r"(__float_as_uint((b)[1])))

/* ============ tf32 mma.sync GEMM: C[m,n] = A[m,:]·W[n,:] + bias[n] ============
   BM=64, BN=128, BK=32, 256 threads, double-buffered cp.async, 3 CTAs/SM. */
#define ASTR 36
#define MT 2
#define STGF ((64 + 128) * ASTR)
#define GSMEM (STGF * 4 * 2)                 /* 55296 bytes */

template<int RELU, int ADDC, int RND, int RC>
__device__ __forceinline__ void gemm_body(const float* __restrict__ A,
                                          const float* __restrict__ W,
                                          const float* __restrict__ bias,
                                          float* __restrict__ C,
                                          float* __restrict__ Caux,
                                          int M, int N, int K) {
    extern __shared__ float smem[];
    int tid = threadIdx.x;
    int lane = tid & 31, wid = tid >> 5;
    int wm = wid & 1, wn = wid >> 1;
    int m0 = blockIdx.y * 64, n0 = blockIdx.x * 128;
    int r0 = lane >> 2, k4 = lane & 3;

    float acc[MT][4][4];
    #pragma unroll
    for (int mt = 0; mt < MT; mt++)
        #pragma unroll
        for (int nt = 0; nt < 4; nt++)
            #pragma unroll
            for (int i = 0; i < 4; i++) acc[mt][nt][i] = 0.f;

    const int KT = K >> 5;

    auto load_stage = [&](int kt, int s) {
        const float* Ag = A + (size_t)m0 * K + (kt << 5);
        const float* Wg = W + (size_t)n0 * K + (kt << 5);
        float* Ab = smem + s * STGF;
        float* Bb = Ab + 64 * ASTR;
        #pragma unroll
        for (int i = 0; i < MT; i++) {
            int idx = tid + (i << 8);
            int r = idx >> 3, c4 = (idx & 7) << 2;
            CP16(s2u(Ab + r * ASTR + c4), Ag + (size_t)r * K + c4);
        }
        #pragma unroll
        for (int i = 0; i < 4; i++) {
            int idx = tid + (i << 8);
            int r = idx >> 3, c4 = (idx & 7) << 2;
            CP16(s2u(Bb + r * ASTR + c4), Wg + (size_t)r * K + c4);
        }
    };

    load_stage(0, 0); CP_COMMIT();

    for (int kt = 0; kt < KT; kt++) {
        int s = kt & 1;
        if (kt + 1 < KT) { load_stage(kt + 1, s ^ 1); CP_COMMIT(); CP_WAIT(1); }
        else             { CP_WAIT(0); }
        __syncthreads();

        const float* Ab = smem + s * STGF + (wm * 32 + r0) * ASTR + k4;
        const float* Bb = smem + s * STGF + 64 * ASTR + (wn * 32 + r0) * ASTR + k4;
        #pragma unroll
        for (int ks = 0; ks < 4; ks++) {
            int kb = ks << 3;
            float af[MT][4], bf[4][2];
            #pragma unroll
            for (int mt = 0; mt < MT; mt++) {
                af[mt][0] = Ab[(mt * 16    ) * ASTR + kb];
                af[mt][1] = Ab[(mt * 16 + 8) * ASTR + kb];
                af[mt][2] = Ab[(mt * 16    ) * ASTR + kb + 4];
                af[mt][3] = Ab[(mt * 16 + 8) * ASTR + kb + 4];
            }
            #pragma unroll
            for (int nt = 0; nt < 4; nt++) {
                bf[nt][0] = Bb[nt * 8 * ASTR + kb];
                bf[nt][1] = Bb[nt * 8 * ASTR + kb + 4];
            }
            #pragma unroll
            for (int mt = 0; mt < MT; mt++)
                #pragma unroll
                for (int nt = 0; nt < 4; nt++)
                    MMA_TF32(acc[mt][nt], af[mt], bf[nt]);
        }
        __syncthreads();
    }

    #pragma unroll
    for (int mt = 0; mt < MT; mt++) {
        int mg = m0 + wm * 32 + mt * 16 + r0;
        #pragma unroll
        for (int nt = 0; nt < 4; nt++) {
            int ng = n0 + wn * 32 + nt * 8 + (k4 << 1);
            float b0 = bias[ng], b1 = bias[ng + 1];
            float* c0p = C + (size_t)mg * N + ng;
            float* c1p = C + (size_t)(mg + 8) * N + ng;
            float o0 = acc[mt][nt][0] + b0, o1 = acc[mt][nt][1] + b1;
            float o2 = acc[mt][nt][2] + b0, o3 = acc[mt][nt][3] + b1;
            if (RELU) {
                o0 = fmaxf(o0, 0.f); o1 = fmaxf(o1, 0.f);
                o2 = fmaxf(o2, 0.f); o3 = fmaxf(o3, 0.f);
            }
            if (ADDC) {
                float2 e0 = *(const float2*)c0p;
                float2 e1 = *(const float2*)c1p;
                o0 += e0.x; o1 += e0.y; o2 += e1.x; o3 += e1.y;
            }
            if (RND) { o0 = rtf32(o0); o1 = rtf32(o1); o2 = rtf32(o2); o3 = rtf32(o3); }
            *(float2*)c0p = make_float2(o0, o1);
            *(float2*)c1p = make_float2(o2, o3);
            if (RC) {
                float* a0p = Caux + (size_t)mg * N + ng;
                float* a1p = Caux + (size_t)(mg + 8) * N + ng;
                *(float2*)a0p = make_float2(rtf32(o0), rtf32(o1));
                *(float2*)a1p = make_float2(rtf32(o2), rtf32(o3));
            }
        }
    }
}

template<int RELU, int ADDC, int RND, int RC>
__global__ __launch_bounds__(256, 3) void mma_gemm(const float* __restrict__ A,
                                                   const float* __restrict__ W,
                                                   const float* __restrict__ bias,
                                                   float* __restrict__ C,
                                                   float* __restrict__ Caux,
                                                   int M, int N, int K) {
    gemm_body<RELU, ADDC, RND, RC>(A, W, bias, C, Caux, M, N, K);
}

__global__ __launch_bounds__(256, 3) void mma_gemm_dual(const float* __restrict__ A0,
                                                        const float* __restrict__ W0,
                                                        const float* __restrict__ b0,
                                                        float* __restrict__ C0,
                                                        const float* __restrict__ A1,
                                                        const float* __restrict__ W1,
                                                        const float* __restrict__ b1,
                                                        float* __restrict__ C1,
                                                        int M, int N, int K) {
    if (blockIdx.z == 0) gemm_body<0, 0, 0, 0>(A0, W0, b0, C0, nullptr, M, N, K);
    else                 gemm_body<0, 0, 0, 0>(A1, W1, b1, C1, nullptr, M, N, K);
}

/* ------- slot init: slots + rounded copy; zero bias buffer ------- */
__global__ void init_slots(const float* __restrict__ noise,
                           const float* __restrict__ mu,
                           const float* __restrict__ logsigma,
                           float* __restrict__ slots,
                           float* __restrict__ srd,
                           float* __restrict__ zero) {
    int idx = blockIdx.x * blockDim.x + threadIdx.x;
    int d = idx & (DIM - 1);
    float v = mu[d] + expf(logsigma[d]) * noise[idx];
    slots[idx] = v;
    srd[idx] = rtf32(v);
    if (idx < DIM) zero[idx] = 0.f;
}

/* ---- merged round-copy of all 4 plain weights (2097152 elems) ---- */
__global__ void rc_all(const float* __restrict__ Wih, const float* __restrict__ Whh,
                       const float* __restrict__ W1,  const float* __restrict__ W2,
                       float* __restrict__ Wihr, float* __restrict__ Whhr,
                       float* __restrict__ W1r,  float* __restrict__ W2r) {
    int i = blockIdx.x * 256 + threadIdx.x;
    const float* s; float* d; int off;
    if (i < 786432)        { s = Wih; d = Wihr; off = i; }
    else if (i < 1572864)  { s = Whh; d = Whhr; off = i - 786432; }
    else if (i < 1835008)  { s = W1;  d = W1r;  off = i - 1572864; }
    else                   { s = W2;  d = W2r;  off = i - 1835008; }
    d[off] = rtf32(s[off]);
}

/* ---- merged transposed round-copy (z selects Wk/Wq/Wv) ---- */
__global__ void rct_all(const float* __restrict__ Wk, const float* __restrict__ Wq,
                        const float* __restrict__ Wv,
                        float* __restrict__ WkT, float* __restrict__ WqT,
                        float* __restrict__ WvT) {
    __shared__ float tile[32][33];
    const float* src = (blockIdx.z == 0) ? Wk : (blockIdx.z == 1) ? Wq : Wv;
    float* dst       = (blockIdx.z == 0) ? WkT : (blockIdx.z == 1) ? WqT : WvT;
    int c0 = blockIdx.x * 32, d0 = blockIdx.y * 32;
    int tx = threadIdx.x & 31, ty = threadIdx.x >> 5;
    #pragma unroll
    for (int i = 0; i < 32; i += 8)
        tile[ty + i][tx] = src[(size_t)(d0 + ty + i) * DIM + c0 + tx];
    __syncthreads();
    #pragma unroll
    for (int i = 0; i < 32; i += 8)
        dst[(size_t)(c0 + ty + i) * DIM + d0 + tx] = rtf32(tile[tx][ty + i]);
}

/* ---- vec_fold: v = bq@Wk, u = bk@Wq, bc = bv@W_ih^T + b_ih, c0 = bq·bk ---- */
__global__ __launch_bounds__(256) void vec_fold(const float* __restrict__ WkT,
                                                const float* __restrict__ WqT,
                                                const float* __restrict__ W_ih,
                                                const float* __restrict__ bq,
                                                const float* __restrict__ bk,
                                                const float* __restrict__ bv,
                                                const float* __restrict__ b_ih,
                                                float* __restrict__ v,
                                                float* __restrict__ u,
                                                float* __restrict__ bc,
                                                float* __restrict__ c0) {
    int gw = blockIdx.x * 8 + (threadIdx.x >> 5);
    int l = threadIdx.x & 31;
    if (gw >= 2561) return;
    const float* row; const float* vec;
    if (gw < 512)       { row = WkT + (size_t)gw * DIM;          vec = bq; }
    else if (gw < 1024) { row = WqT + (size_t)(gw - 512) * DIM;  vec = bk; }
    else if (gw < 2560) { row = W_ih + (size_t)(gw - 1024) * DIM; vec = bv; }
    else                { row = bq;                               vec = bk; }
    float s = 0.f;
    for (int c = l; c < DIM; c += 32) s += row[c] * vec[c];
    #pragma unroll
    for (int o = 16; o > 0; o >>= 1) s += __shfl_down_sync(0xffffffffu, s, o);
    if (l == 0) {
        if (gw < 512) v[gw] = s;
        else if (gw < 1024) u[gw - 512] = s;
        else if (gw < 2560) bc[gw - 1024] = s + b_ih[gw - 1024];
        else c0[0] = s;
    }
}

/* ---------------- row LayerNorm (inputs variant) ---------------- */
__global__ void ln_rows(const float* __restrict__ in, float* __restrict__ out,
                        const float* __restrict__ gamma, const float* __restrict__ beta) {
    int row = blockIdx.x;
    int t = threadIdx.x;
    const float4* ip = (const float4*)(in + (size_t)row * DIM);
    float4 x = ip[t];
    float s  = x.x + x.y + x.z + x.w;
    float ss = x.x*x.x + x.y*x.y + x.z*x.z + x.w*x.w;
    #pragma unroll
    for (int o = 16; o > 0; o >>= 1) {
        s  += __shfl_down_sync(0xffffffffu, s,  o);
        ss += __shfl_down_sync(0xffffffffu, ss, o);
    }
    __shared__ float sh[8];
    int w = t >> 5, l = t & 31;
    if (l == 0) { sh[w] = s; sh[4 + w] = ss; }
    __syncthreads();
    s  = sh[0] + sh[1] + sh[2] + sh[3];
    ss = sh[4] + sh[5] + sh[6] + sh[7];
    float mean = s * (1.0f / DIM);
    float var  = ss * (1.0f / DIM) - mean * mean;
    float rstd = rsqrtf(var + LN_EPS);
    float4 g = ((const float4*)gamma)[t];
    float4 b = ((const float4*)beta)[t];
    float4 o4;
    o4.x = rtf32((x.x - mean) * rstd * g.x + b.x);
    o4.y = rtf32((x.y - mean) * rstd * g.y + b.y);
    o4.z = rtf32((x.z - mean) * rstd * g.z + b.z);
    o4.w = rtf32((x.w - mean) * rstd * g.w + b.w);
    ((float4*)(out + (size_t)row * DIM))[t] = o4;
}

/* ---- slot LayerNorm + fused qbk = out·u + c0 ---- */
__global__ void ln_rows_q(const float* __restrict__ in, float* __restrict__ out,
                          const float* __restrict__ gamma, const float* __restrict__ beta,
                          const float* __restrict__ u, const float* __restrict__ c0,
                          float* __restrict__ qbk) {
    int row = blockIdx.x;
    int t = threadIdx.x;
    const float4* ip = (const float4*)(in + (size_t)row * DIM);
    float4 x = ip[t];
    float s  = x.x + x.y + x.z + x.w;
    float ss = x.x*x.x + x.y*x.y + x.z*x.z + x.w*x.w;
    #pragma unroll
    for (int o = 16; o > 0; o >>= 1) {
        s  += __shfl_down_sync(0xffffffffu, s,  o);
        ss += __shfl_down_sync(0xffffffffu, ss, o);
    }
    __shared__ float sh[8];
    __shared__ float sh2[4];
    int w = t >> 5, l = t & 31;
    if (l == 0) { sh[w] = s; sh[4 + w] = ss; }
    __syncthreads();
    s  = sh[0] + sh[1] + sh[2] + sh[3];
    ss = sh[4] + sh[5] + sh[6] + sh[7];
    float mean = s * (1.0f / DIM);
    float var  = ss * (1.0f / DIM) - mean * mean;
    float rstd = rsqrtf(var + LN_EPS);
    float4 g = ((const float4*)gamma)[t];
    float4 b = ((const float4*)beta)[t];
    float4 o4;
    o4.x = rtf32((x.x - mean) * rstd * g.x + b.x);
    o4.y = rtf32((x.y - mean) * rstd * g.y + b.y);
    o4.z = rtf32((x.z - mean) * rstd * g.z + b.z);
    o4.w = rtf32((x.w - mean) * rstd * g.w + b.w);
    ((float4*)(out + (size_t)row * DIM))[t] = o4;
    float4 uv = ((const float4*)u)[t];
    float sv = o4.x*uv.x + o4.y*uv.y + o4.z*uv.z + o4.w*uv.w;
    #pragma unroll
    for (int o = 16; o > 0; o >>= 1) sv += __shfl_down_sync(0xffffffffu, sv, o);
    if (l == 0) sh2[w] = sv;
    __syncthreads();
    if (t == 0) qbk[row] = sh2[0] + sh2[1] + sh2[2] + sh2[3] + c0[0];
}

/* ==== fused attention: dots + softmax + partial V-contraction.
   grid (8, BATCH), 128 threads. Outputs paw, prs (reduced separately). ==== */
#define KSTR 36
__global__ __launch_bounds__(128) void attn_fused(const float* __restrict__ xn,
                                                  const float* __restrict__ qkmat,
                                                  const float* __restrict__ qbk,
                                                  float* __restrict__ paw,
                                                  float* __restrict__ prs) {
    int b = blockIdx.y, blk = blockIdx.x;
    int j0 = blk * 128;
    int tid = threadIdx.x;
    __shared__ __align__(16) float qs[NS][DIM];      /* 16 KB */
    __shared__ __align__(16) float kch[128][KSTR];   /* 18 KB */
    __shared__ __align__(16) float as[NS][128];      /* 4 KB  */
    __shared__ float qb[NS];
    __shared__ float rsm[NS][4];

    {
        const float4* qsrc = (const float4*)(qkmat + (size_t)b * NS * DIM);
        for (int idx = tid; idx < NS * DIM / 4; idx += 128) {
            float4 vv = qsrc[idx];
            int i = idx >> 7, d4 = idx & 127;
            qs[i][d4*4+0] = vv.x; qs[i][d4*4+1] = vv.y;
            qs[i][d4*4+2] = vv.z; qs[i][d4*4+3] = vv.w;
        }
        if (tid < NS) qb[tid] = qbk[b * NS + tid];
    }

    float acc[NS];
    const float* kbase = xn + (size_t)(b * NTOK + j0) * DIM;

    for (int dc = 0; dc < DIM; dc += 32) {
        __syncthreads();
        #pragma unroll
        for (int ii = 0; ii < 8; ii++) {
            int idx = tid + ii * 128;
            int r = idx >> 3, c4 = idx & 7;
            float4 vv = *(const float4*)(kbase + (size_t)r * DIM + dc + c4 * 4);
            *(float4*)&kch[r][c4 * 4] = vv;
        }
        __syncthreads();
        if (dc == 0) {
            #pragma unroll
            for (int i = 0; i < NS; i++) acc[i] = qb[i];
        }
        #pragma unroll
        for (int c4 = 0; c4 < 8; c4++) {
            float4 k4 = *(const float4*)&kch[tid][c4 * 4];
            #pragma unroll
            for (int i = 0; i < NS; i++) {
                float4 q4 = *(const float4*)&qs[i][dc + c4 * 4];
                acc[i] += k4.x*q4.x + k4.y*q4.y + k4.z*q4.z + k4.w*q4.w;
            }
        }
    }

    float m = -1e30f;
    #pragma unroll
    for (int i = 0; i < NS; i++) { acc[i] *= ATT_SCALE; m = fmaxf(m, acc[i]); }
    float sum = 0.f;
    #pragma unroll
    for (int i = 0; i < NS; i++) { acc[i] = expf(acc[i] - m); sum += acc[i]; }
    float inv = 1.0f / sum;
    int w = tid >> 5, l = tid & 31;
    #pragma unroll
    for (int i = 0; i < NS; i++) {
        float p = acc[i] * inv + ATT_EPS;
        as[i][tid] = p;
        float s = p;
        #pragma unroll
        for (int o = 16; o > 0; o >>= 1) s += __shfl_down_sync(0xffffffffu, s, o);
        if (l == 0) rsm[i][w] = s;
    }
    __syncthreads();
    if (tid < NS)
        prs[((size_t)b * 8 + blk) * NS + tid] = rsm[tid][0] + rsm[tid][1] + rsm[tid][2] + rsm[tid][3];

    int i0 = w, i1 = w + 4;
    float* pout0 = paw + (((size_t)b * 8 + blk) * NS + i0) * DIM;
    float* pout1 = paw + (((size_t)b * 8 + blk) * NS + i1) * DIM;
    for (int dc = 0; dc < DIM; dc += 32) {
        __syncthreads();
        #pragma unroll
        for (int ii = 0; ii < 8; ii++) {
            int idx = tid + ii * 128;
            int r = idx >> 3, c4 = idx & 7;
            float4 vv = *(const float4*)(kbase + (size_t)r * DIM + dc + c4 * 4);
            *(float4*)&kch[r][c4 * 4] = vv;
        }
        __syncthreads();
        float f0 = 0.f, f1 = 0.f;
        #pragma unroll 8
        for (int j4 = 0; j4 < 32; j4++) {
            float4 a0 = *(const float4*)&as[i0][j4 * 4];
            float4 a1 = *(const float4*)&as[i1][j4 * 4];
            float k0 = kch[j4*4 + 0][l], k1 = kch[j4*4 + 1][l];
            float k2 = kch[j4*4 + 2][l], k3 = kch[j4*4 + 3][l];
            f0 += a0.x*k0 + a0.y*k1 + a0.z*k2 + a0.w*k3;
            f1 += a1.x*k0 + a1.y*k1 + a1.z*k2 + a1.w*k3;
        }
        pout0[dc + l] = f0;
        pout1[dc + l] = f1;
    }
}

/* ---- reduce partials: awn[b,i,c] = rtf32( sum_blk paw / sum_blk prs ) ---- */
__global__ __launch_bounds__(512) void attn_reduce(const float* __restrict__ paw,
                                                   const float* __restrict__ prs,
                                                   float* __restrict__ awn) {
    int b = blockIdx.x;
    int c = threadIdx.x;
    __shared__ float rs[NS];
    if (c < NS) {
        float s = 0.f;
        #pragma unroll
        for (int blk = 0; blk < 8; blk++)
            s += prs[((size_t)b * 8 + blk) * NS + c];
        rs[c] = 1.0f / s;
    }
    __syncthreads();
    #pragma unroll
    for (int i = 0; i < NS; i++) {
        float s = 0.f;
        #pragma unroll
        for (int blk = 0; blk < 8; blk++)
            s += paw[(((size_t)b * 8 + blk) * NS + i) * DIM + c];
        awn[((size_t)b * NS + i) * DIM + c] = rtf32(s * rs[i]);
    }
}

/* ---- fused GRU gate + LayerNorm(ff) ---- */
__global__ __launch_bounds__(512) void gru_ln(const float* __restrict__ xg,
                                              const float* __restrict__ hg,
                                              float* __restrict__ slots,
                                              float* __restrict__ sbuf,
                                              const float* __restrict__ gamma,
                                              const float* __restrict__ beta) {
    int row = blockIdx.x;
    int c = threadIdx.x;
    size_t base = (size_t)row * 3 * DIM;
    float xr = xg[base + c],         hr = hg[base + c];
    float xz = xg[base + DIM + c],   hz = hg[base + DIM + c];
    float xn = xg[base + 2*DIM + c], hn = hg[base + 2*DIM + c];
    float r = 1.0f / (1.0f + expf(-(xr + hr)));
    float z = 1.0f / (1.0f + expf(-(xz + hz)));
    float n = tanhf(xn + r * hn);
    size_t si = (size_t)row * DIM + c;
    float prev = slots[si];
    float v = (1.0f - z) * n + z * prev;
    slots[si] = v;

    __shared__ float sh[32];
    float s = v, ss = v * v;
    #pragma unroll
    for (int o = 16; o > 0; o >>= 1) {
        s  += __shfl_down_sync(0xffffffffu, s,  o);
        ss += __shfl_down_sync(0xffffffffu, ss, o);
    }
    int w = c >> 5, l = c & 31;
    if (l == 0) { sh[w] = s; sh[16 + w] = ss; }
    __syncthreads();
    float ts = 0.f, tss = 0.f;
    #pragma unroll
    for (int i = 0; i < 16; i++) { ts += sh[i]; tss += sh[16 + i]; }
    float mean = ts * (1.0f / DIM);
    float var  = tss * (1.0f / DIM) - mean * mean;
    float rstd = rsqrtf(var + LN_EPS);
    sbuf[si] = rtf32((v - mean) * rstd * gamma[c] + beta[c]);
}

/* ---------------- host ---------------- */
static float* sym(const void* s) {
    void* p = nullptr;
    cudaGetSymbolAddress(&p, s);
    return (float*)p;
}

extern "C" void kernel_launch(void* const* d_in, const int* in_sizes, int n_in,
                              void* d_out, int out_size) {
    const float* inputs    = (const float*)d_in[0];
    const float* noise     = (const float*)d_in[1];
    const float* mu        = (const float*)d_in[2];
    const float* logsigma  = (const float*)d_in[3];
    const float* gi        = (const float*)d_in[4];
    const float* bei       = (const float*)d_in[5];
    const float* gsl       = (const float*)d_in[6];
    const float* besl      = (const float*)d_in[7];
    const float* gff       = (const float*)d_in[8];
    const float* beff      = (const float*)d_in[9];
    const float* Wq        = (const float*)d_in[10];
    const float* bq        = (const float*)d_in[11];
    const float* Wk        = (const float*)d_in[12];
    const float* bk        = (const float*)d_in[13];
    const float* Wv        = (const float*)d_in[14];
    const float* bv        = (const float*)d_in[15];
    const float* W_ih      = (const float*)d_in[16];
    const float* b_ih      = (const float*)d_in[17];
    const float* W_hh      = (const float*)d_in[18];
    const float* b_hh      = (const float*)d_in[19];
    const float* W1        = (const float*)d_in[20];
    const float* b1        = (const float*)d_in[21];
    const float* W2        = (const float*)d_in[22];
    const float* b2        = (const float*)d_in[23];
    float* slots = (float*)d_out;

    float* xn   = sym(g_xn);
    float* WkT  = sym(g_WkT);
    float* WqT  = sym(g_WqT);
    float* WvT  = sym(g_WvT);
    float* Wp   = sym(g_Wp);
    float* Wc   = sym(g_Wc);
    float* Wihr = sym(g_Wih_r);
    float* Whhr = sym(g_Whh_r);
    float* W1r  = sym(g_W1_r);
    float* W2r  = sym(g_W2_r);
    float* zero = sym(g_zero);
    float* vv   = sym(g_v);
    float* uu   = sym(g_u);
    float* c0   = sym(g_c0);
    float* bc   = sym(g_bc);
    float* sbuf = sym(g_s);
    float* srd  = sym(g_sr);
    float* qk   = sym(g_qk);
    float* qbk  = sym(g_qbk);
    float* paw  = sym(g_paw);
    float* prs  = sym(g_prs);
    float* awn  = sym(g_awn);
    float* xg   = sym(g_xg);
    float* hg   = sym(g_hg);
    float* hid  = sym(g_hid);

    cudaFuncSetAttribute(mma_gemm<0,0,0,0>, cudaFuncAttributeMaxDynamicSharedMemorySize, GSMEM);
    cudaFuncSetAttribute(mma_gemm<0,0,1,0>, cudaFuncAttributeMaxDynamicSharedMemorySize, GSMEM);
    cudaFuncSetAttribute(mma_gemm<1,0,1,0>, cudaFuncAttributeMaxDynamicSharedMemorySize, GSMEM);
    cudaFuncSetAttribute(mma_gemm<0,1,0,1>, cudaFuncAttributeMaxDynamicSharedMemorySize, GSMEM);
    cudaFuncSetAttribute(mma_gemm_dual,     cudaFuncAttributeMaxDynamicSharedMemorySize, GSMEM);

    /* launch #4 = DIAGNOSTIC attn_fused on previous-replay data (device
       globals are replay-invariant); outputs overwritten by iter-1's real
       attn_fused before attn_reduce consumes them. */
    init_slots<<<SROWS*DIM/256, 256>>>(noise, mu, logsigma, slots, srd, zero); /* 1 */
    rct_all<<<dim3(16,16,3), 256>>>(Wk, Wq, Wv, WkT, WqT, WvT);                /* 2 */
    rc_all<<<2097152/256, 256>>>(W_ih, W_hh, W1, W2, Wihr, Whhr, W1r, W2r);    /* 3 */
    attn_fused<<<dim3(8, BATCH), 128>>>(xn, qk, qbk, paw, prs);                /* 4: PROFILED */
    ln_rows<<<NROWS, 128>>>(inputs, xn, gi, bei);                              /* 5 */
    mma_gemm<0,0,1,0><<<dim3(DIM/128, DIM/64), 256, GSMEM>>>(WkT, WqT, zero, Wp, nullptr, DIM, DIM, DIM);
    mma_gemm<0,0,1,0><<<dim3(DIM/128, 3*DIM/64), 256, GSMEM>>>(Wihr, WvT, zero, Wc, nullptr, 3*DIM, DIM, DIM);
    vec_fold<<<321, 256>>>(WkT, WqT, W_ih, bq, bk, bv, b_ih, vv, uu, bc, c0);

    for (int it = 0; it < 3; it++) {
        ln_rows_q<<<SROWS, 128>>>(slots, sbuf, gsl, besl, uu, c0, qbk);
        mma_gemm<0,0,0,0><<<dim3(DIM/128, SROWS/64), 256, GSMEM>>>(sbuf, Wp, vv, qk, nullptr, SROWS, DIM, DIM);
        attn_fused<<<dim3(8, BATCH), 128>>>(xn, qk, qbk, paw, prs);
        attn_reduce<<<BATCH, 512>>>(paw, prs, awn);
        mma_gemm_dual<<<dim3(3*DIM/128, SROWS/64, 2), 256, GSMEM>>>(
            awn, Wc, bc, xg, srd, Whhr, b_hh, hg, SROWS, 3*DIM, DIM);
        gru_ln<<<SROWS, 512>>>(xg, hg, slots, sbuf, gff, beff);
        mma_gemm<1,0,1,0><<<dim3(HIDN/128, SROWS/64), 256, GSMEM>>>(sbuf, W1r, b1, hid, nullptr, SROWS, HIDN, DIM);
        mma_gemm<0,1,0,1><<<dim3(DIM/128, SROWS/64), 256, GSMEM>>>(hid, W2r, b2, slots, srd, SROWS, DIM, HIDN);
    }
    (void)in_sizes; (void)n_in; (void)out_size;
}

// round 15
// speedup vs baseline: 1.3333x; 1.3333x over previous
#include <cuda_runtime.h>
#include <math.h>
#include <stdint.h>

#define DIM   512
#define NS    8
#define BATCH 128
#define NTOK  1024
#define HIDN  512
#define NROWS (BATCH*NTOK)   /* 131072 */
#define SROWS (BATCH*NS)     /* 1024   */
#define ATT_SCALE 0.04419417382415922f
#define LN_EPS 1e-5f
#define ATT_EPS 1e-8f

/* ---------------- scratch (device globals; no allocation) ---------------- */
__device__ float g_xn[(size_t)NROWS*DIM];
__device__ float g_WkT[DIM*DIM];
__device__ float g_WqT[DIM*DIM];
__device__ float g_WvT[DIM*DIM];
__device__ float g_Wp[DIM*DIM];          /* (Wq^T Wk) as W-operand layout */
__device__ float g_Wc[3*DIM*DIM];        /* Wih @ Wv */
__device__ float g_Wih_r[3*DIM*DIM];
__device__ float g_Whh_r[3*DIM*DIM];
__device__ float g_W1_r[HIDN*DIM];
__device__ float g_W2_r[DIM*HIDN];
__device__ float g_zero[DIM];
__device__ float g_v[DIM];
__device__ float g_u[DIM];
__device__ float g_c0[1];
__device__ float g_bc[3*DIM];
__device__ float g_s [SROWS*DIM];
__device__ float g_sr[SROWS*DIM];
__device__ float g_qk[SROWS*DIM];
__device__ float g_qbk[SROWS];
__device__ float g_paw[(size_t)BATCH*8*NS*DIM];   /* [b][blk][i][c], 16 MB */
__device__ float g_prs[BATCH*8*NS];
__device__ float g_awn[SROWS*DIM];
__device__ float g_xg[SROWS*3*DIM];
__device__ float g_hg[SROWS*3*DIM];
__device__ float g_hid[SROWS*HIDN];

/* ---------------- helpers ---------------- */
__device__ __forceinline__ float rtf32(float x) {
    uint32_t u; asm("cvt.rna.tf32.f32 %0, %1;" : "=r"(u) : "f"(x));
    return __uint_as_float(u);
}
__device__ __forceinline__ uint32_t s2u(const void* p) {
    uint32_t a;
    asm("{ .reg .u64 t; cvta.to.shared.u64 t, %1; cvt.u32.u64 %0, t; }" : "=r"(a) : "l"(p));
    return a;
}

#define CP16(dst, src) \
    asm volatile("cp.async.cg.shared.global [%0], [%1], 16;" :: "r"(dst), "l"(src))
#define CP_COMMIT() asm volatile("cp.async.commit_group;" ::: "memory")
#define CP_WAIT(n)  asm volatile("cp.async.wait_group %0;" :: "n"(n) : "memory")

#define MMA_TF32(d, a, b) \
    asm volatile("mma.sync.aligned.m16n8k8.row.col.f32.tf32.tf32.f32 " \
        "{%0,%1,%2,%3}, {%4,%5,%6,%7}, {%8,%9}, {%0,%1,%2,%3};" \
        : "+f"((d)[0]), "+f"((d)[1]), "+f"((d)[2]), "+f"((d)[3]) \
        : "r"(__float_as_uint((a)[0])), "r"(__float_as_uint((a)[1])), \
          "r"(__float_as_uint((a)[2])), "r"(__float_as_uint((a)[3])), \
          "r"(__float_as_uint((b)[0])), "r"(__float_as_uint((b)[1])))

/* ============ tf32 mma.sync GEMM: C[m,n] = A[m,:]·W[n,:] + bias[n] ============
   BM=64, BN=128, BK=32, 256 threads, double-buffered cp.async, 3 CTAs/SM. */
#define ASTR 36
#define MT 2
#define STGF ((64 + 128) * ASTR)
#define GSMEM (STGF * 4 * 2)                 /* 55296 bytes */

template<int RELU, int ADDC, int RND, int RC>
__device__ __forceinline__ void gemm_body(const float* __restrict__ A,
                                          const float* __restrict__ W,
                                          const float* __restrict__ bias,
                                          float* __restrict__ C,
                                          float* __restrict__ Caux,
                                          int M, int N, int K) {
    extern __shared__ float smem[];
    int tid = threadIdx.x;
    int lane = tid & 31, wid = tid >> 5;
    int wm = wid & 1, wn = wid >> 1;
    int m0 = blockIdx.y * 64, n0 = blockIdx.x * 128;
    int r0 = lane >> 2, k4 = lane & 3;

    float acc[MT][4][4];
    #pragma unroll
    for (int mt = 0; mt < MT; mt++)
        #pragma unroll
        for (int nt = 0; nt < 4; nt++)
            #pragma unroll
            for (int i = 0; i < 4; i++) acc[mt][nt][i] = 0.f;

    const int KT = K >> 5;

    auto load_stage = [&](int kt, int s) {
        const float* Ag = A + (size_t)m0 * K + (kt << 5);
        const float* Wg = W + (size_t)n0 * K + (kt << 5);
        float* Ab = smem + s * STGF;
        float* Bb = Ab + 64 * ASTR;
        #pragma unroll
        for (int i = 0; i < MT; i++) {
            int idx = tid + (i << 8);
            int r = idx >> 3, c4 = (idx & 7) << 2;
            CP16(s2u(Ab + r * ASTR + c4), Ag + (size_t)r * K + c4);
        }
        #pragma unroll
        for (int i = 0; i < 4; i++) {
            int idx = tid + (i << 8);
            int r = idx >> 3, c4 = (idx & 7) << 2;
            CP16(s2u(Bb + r * ASTR + c4), Wg + (size_t)r * K + c4);
        }
    };

    load_stage(0, 0); CP_COMMIT();

    for (int kt = 0; kt < KT; kt++) {
        int s = kt & 1;
        if (kt + 1 < KT) { load_stage(kt + 1, s ^ 1); CP_COMMIT(); CP_WAIT(1); }
        else             { CP_WAIT(0); }
        __syncthreads();

        const float* Ab = smem + s * STGF + (wm * 32 + r0) * ASTR + k4;
        const float* Bb = smem + s * STGF + 64 * ASTR + (wn * 32 + r0) * ASTR + k4;
        #pragma unroll
        for (int ks = 0; ks < 4; ks++) {
            int kb = ks << 3;
            float af[MT][4], bf[4][2];
            #pragma unroll
            for (int mt = 0; mt < MT; mt++) {
                af[mt][0] = Ab[(mt * 16    ) * ASTR + kb];
                af[mt][1] = Ab[(mt * 16 + 8) * ASTR + kb];
                af[mt][2] = Ab[(mt * 16    ) * ASTR + kb + 4];
                af[mt][3] = Ab[(mt * 16 + 8) * ASTR + kb + 4];
            }
            #pragma unroll
            for (int nt = 0; nt < 4; nt++) {
                bf[nt][0] = Bb[nt * 8 * ASTR + kb];
                bf[nt][1] = Bb[nt * 8 * ASTR + kb + 4];
            }
            #pragma unroll
            for (int mt = 0; mt < MT; mt++)
                #pragma unroll
                for (int nt = 0; nt < 4; nt++)
                    MMA_TF32(acc[mt][nt], af[mt], bf[nt]);
        }
        __syncthreads();
    }

    #pragma unroll
    for (int mt = 0; mt < MT; mt++) {
        int mg = m0 + wm * 32 + mt * 16 + r0;
        #pragma unroll
        for (int nt = 0; nt < 4; nt++) {
            int ng = n0 + wn * 32 + nt * 8 + (k4 << 1);
            float b0 = bias[ng], b1 = bias[ng + 1];
            float* c0p = C + (size_t)mg * N + ng;
            float* c1p = C + (size_t)(mg + 8) * N + ng;
            float o0 = acc[mt][nt][0] + b0, o1 = acc[mt][nt][1] + b1;
            float o2 = acc[mt][nt][2] + b0, o3 = acc[mt][nt][3] + b1;
            if (RELU) {
                o0 = fmaxf(o0, 0.f); o1 = fmaxf(o1, 0.f);
                o2 = fmaxf(o2, 0.f); o3 = fmaxf(o3, 0.f);
            }
            if (ADDC) {
                float2 e0 = *(const float2*)c0p;
                float2 e1 = *(const float2*)c1p;
                o0 += e0.x; o1 += e0.y; o2 += e1.x; o3 += e1.y;
            }
            if (RND) { o0 = rtf32(o0); o1 = rtf32(o1); o2 = rtf32(o2); o3 = rtf32(o3); }
            *(float2*)c0p = make_float2(o0, o1);
            *(float2*)c1p = make_float2(o2, o3);
            if (RC) {
                float* a0p = Caux + (size_t)mg * N + ng;
                float* a1p = Caux + (size_t)(mg + 8) * N + ng;
                *(float2*)a0p = make_float2(rtf32(o0), rtf32(o1));
                *(float2*)a1p = make_float2(rtf32(o2), rtf32(o3));
            }
        }
    }
}

template<int RELU, int ADDC, int RND, int RC>
__global__ __launch_bounds__(256, 3) void mma_gemm(const float* __restrict__ A,
                                                   const float* __restrict__ W,
                                                   const float* __restrict__ bias,
                                                   float* __restrict__ C,
                                                   float* __restrict__ Caux,
                                                   int M, int N, int K) {
    gemm_body<RELU, ADDC, RND, RC>(A, W, bias, C, Caux, M, N, K);
}

__global__ __launch_bounds__(256, 3) void mma_gemm_dual(const float* __restrict__ A0,
                                                        const float* __restrict__ W0,
                                                        const float* __restrict__ b0,
                                                        float* __restrict__ C0,
                                                        const float* __restrict__ A1,
                                                        const float* __restrict__ W1,
                                                        const float* __restrict__ b1,
                                                        float* __restrict__ C1,
                                                        int M, int N, int K) {
    if (blockIdx.z == 0) gemm_body<0, 0, 0, 0>(A0, W0, b0, C0, nullptr, M, N, K);
    else                 gemm_body<0, 0, 0, 0>(A1, W1, b1, C1, nullptr, M, N, K);
}

/* ------- slot init: slots + rounded copy; zero bias buffer ------- */
__global__ void init_slots(const float* __restrict__ noise,
                           const float* __restrict__ mu,
                           const float* __restrict__ logsigma,
                           float* __restrict__ slots,
                           float* __restrict__ srd,
                           float* __restrict__ zero) {
    int idx = blockIdx.x * blockDim.x + threadIdx.x;
    int d = idx & (DIM - 1);
    float v = mu[d] + expf(logsigma[d]) * noise[idx];
    slots[idx] = v;
    srd[idx] = rtf32(v);
    if (idx < DIM) zero[idx] = 0.f;
}

/* ---- merged round-copy of all 4 plain weights (2097152 elems) ---- */
__global__ void rc_all(const float* __restrict__ Wih, const float* __restrict__ Whh,
                       const float* __restrict__ W1,  const float* __restrict__ W2,
                       float* __restrict__ Wihr, float* __restrict__ Whhr,
                       float* __restrict__ W1r,  float* __restrict__ W2r) {
    int i = blockIdx.x * 256 + threadIdx.x;
    const float* s; float* d; int off;
    if (i < 786432)        { s = Wih; d = Wihr; off = i; }
    else if (i < 1572864)  { s = Whh; d = Whhr; off = i - 786432; }
    else if (i < 1835008)  { s = W1;  d = W1r;  off = i - 1572864; }
    else                   { s = W2;  d = W2r;  off = i - 1835008; }
    d[off] = rtf32(s[off]);
}

/* ---- merged transposed round-copy (z selects Wk/Wq/Wv) ---- */
__global__ void rct_all(const float* __restrict__ Wk, const float* __restrict__ Wq,
                        const float* __restrict__ Wv,
                        float* __restrict__ WkT, float* __restrict__ WqT,
                        float* __restrict__ WvT) {
    __shared__ float tile[32][33];
    const float* src = (blockIdx.z == 0) ? Wk : (blockIdx.z == 1) ? Wq : Wv;
    float* dst       = (blockIdx.z == 0) ? WkT : (blockIdx.z == 1) ? WqT : WvT;
    int c0 = blockIdx.x * 32, d0 = blockIdx.y * 32;
    int tx = threadIdx.x & 31, ty = threadIdx.x >> 5;
    #pragma unroll
    for (int i = 0; i < 32; i += 8)
        tile[ty + i][tx] = src[(size_t)(d0 + ty + i) * DIM + c0 + tx];
    __syncthreads();
    #pragma unroll
    for (int i = 0; i < 32; i += 8)
        dst[(size_t)(c0 + ty + i) * DIM + d0 + tx] = rtf32(tile[tx][ty + i]);
}

/* ---- vec_fold: v = bq@Wk, u = bk@Wq, bc = bv@W_ih^T + b_ih, c0 = bq·bk ---- */
__global__ __launch_bounds__(256) void vec_fold(const float* __restrict__ WkT,
                                                const float* __restrict__ WqT,
                                                const float* __restrict__ W_ih,
                                                const float* __restrict__ bq,
                                                const float* __restrict__ bk,
                                                const float* __restrict__ bv,
                                                const float* __restrict__ b_ih,
                                                float* __restrict__ v,
                                                float* __restrict__ u,
                                                float* __restrict__ bc,
                                                float* __restrict__ c0) {
    int gw = blockIdx.x * 8 + (threadIdx.x >> 5);
    int l = threadIdx.x & 31;
    if (gw >= 2561) return;
    const float* row; const float* vec;
    if (gw < 512)       { row = WkT + (size_t)gw * DIM;          vec = bq; }
    else if (gw < 1024) { row = WqT + (size_t)(gw - 512) * DIM;  vec = bk; }
    else if (gw < 2560) { row = W_ih + (size_t)(gw - 1024) * DIM; vec = bv; }
    else                { row = bq;                               vec = bk; }
    float s = 0.f;
    for (int c = l; c < DIM; c += 32) s += row[c] * vec[c];
    #pragma unroll
    for (int o = 16; o > 0; o >>= 1) s += __shfl_down_sync(0xffffffffu, s, o);
    if (l == 0) {
        if (gw < 512) v[gw] = s;
        else if (gw < 1024) u[gw - 512] = s;
        else if (gw < 2560) bc[gw - 1024] = s + b_ih[gw - 1024];
        else c0[0] = s;
    }
}

/* ---------------- row LayerNorm (inputs variant) ---------------- */
__global__ void ln_rows(const float* __restrict__ in, float* __restrict__ out,
                        const float* __restrict__ gamma, const float* __restrict__ beta) {
    int row = blockIdx.x;
    int t = threadIdx.x;
    const float4* ip = (const float4*)(in + (size_t)row * DIM);
    float4 x = ip[t];
    float s  = x.x + x.y + x.z + x.w;
    float ss = x.x*x.x + x.y*x.y + x.z*x.z + x.w*x.w;
    #pragma unroll
    for (int o = 16; o > 0; o >>= 1) {
        s  += __shfl_down_sync(0xffffffffu, s,  o);
        ss += __shfl_down_sync(0xffffffffu, ss, o);
    }
    __shared__ float sh[8];
    int w = t >> 5, l = t & 31;
    if (l == 0) { sh[w] = s; sh[4 + w] = ss; }
    __syncthreads();
    s  = sh[0] + sh[1] + sh[2] + sh[3];
    ss = sh[4] + sh[5] + sh[6] + sh[7];
    float mean = s * (1.0f / DIM);
    float var  = ss * (1.0f / DIM) - mean * mean;
    float rstd = rsqrtf(var + LN_EPS);
    float4 g = ((const float4*)gamma)[t];
    float4 b = ((const float4*)beta)[t];
    float4 o4;
    o4.x = rtf32((x.x - mean) * rstd * g.x + b.x);
    o4.y = rtf32((x.y - mean) * rstd * g.y + b.y);
    o4.z = rtf32((x.z - mean) * rstd * g.z + b.z);
    o4.w = rtf32((x.w - mean) * rstd * g.w + b.w);
    ((float4*)(out + (size_t)row * DIM))[t] = o4;
}

/* ---- slot LayerNorm + fused qbk = out·u + c0 ---- */
__global__ void ln_rows_q(const float* __restrict__ in, float* __restrict__ out,
                          const float* __restrict__ gamma, const float* __restrict__ beta,
                          const float* __restrict__ u, const float* __restrict__ c0,
                          float* __restrict__ qbk) {
    int row = blockIdx.x;
    int t = threadIdx.x;
    const float4* ip = (const float4*)(in + (size_t)row * DIM);
    float4 x = ip[t];
    float s  = x.x + x.y + x.z + x.w;
    float ss = x.x*x.x + x.y*x.y + x.z*x.z + x.w*x.w;
    #pragma unroll
    for (int o = 16; o > 0; o >>= 1) {
        s  += __shfl_down_sync(0xffffffffu, s,  o);
        ss += __shfl_down_sync(0xffffffffu, ss, o);
    }
    __shared__ float sh[8];
    __shared__ float sh2[4];
    int w = t >> 5, l = t & 31;
    if (l == 0) { sh[w] = s; sh[4 + w] = ss; }
    __syncthreads();
    s  = sh[0] + sh[1] + sh[2] + sh[3];
    ss = sh[4] + sh[5] + sh[6] + sh[7];
    float mean = s * (1.0f / DIM);
    float var  = ss * (1.0f / DIM) - mean * mean;
    float rstd = rsqrtf(var + LN_EPS);
    float4 g = ((const float4*)gamma)[t];
    float4 b = ((const float4*)beta)[t];
    float4 o4;
    o4.x = rtf32((x.x - mean) * rstd * g.x + b.x);
    o4.y = rtf32((x.y - mean) * rstd * g.y + b.y);
    o4.z = rtf32((x.z - mean) * rstd * g.z + b.z);
    o4.w = rtf32((x.w - mean) * rstd * g.w + b.w);
    ((float4*)(out + (size_t)row * DIM))[t] = o4;
    float4 uv = ((const float4*)u)[t];
    float sv = o4.x*uv.x + o4.y*uv.y + o4.z*uv.z + o4.w*uv.w;
    #pragma unroll
    for (int o = 16; o > 0; o >>= 1) sv += __shfl_down_sync(0xffffffffu, sv, o);
    if (l == 0) sh2[w] = sv;
    __syncthreads();
    if (t == 0) qbk[row] = sh2[0] + sh2[1] + sh2[2] + sh2[3] + c0[0];
}

/* ==== fused attention: dots + softmax + partial V-contraction.
   grid (8, BATCH), 128 threads.
   Stage 3 restructured: warp w owns cols [128w,128w+128), lane a float4;
   xn read directly from global (L2-hot after stage 1), attn broadcast from
   transposed as_t[128][12]. ==== */
#define KSTR 36
__global__ __launch_bounds__(128) void attn_fused(const float* __restrict__ xn,
                                                  const float* __restrict__ qkmat,
                                                  const float* __restrict__ qbk,
                                                  float* __restrict__ paw,
                                                  float* __restrict__ prs) {
    int b = blockIdx.y, blk = blockIdx.x;
    int j0 = blk * 128;
    int tid = threadIdx.x;
    __shared__ __align__(16) float qs[NS][DIM];      /* 16 KB */
    __shared__ __align__(16) float kch[128][KSTR];   /* 18 KB */
    __shared__ __align__(16) float as_t[128][12];    /* 6 KB, 48B rows (16B-aligned) */
    __shared__ float qb[NS];
    __shared__ float rsm[NS][4];

    {
        const float4* qsrc = (const float4*)(qkmat + (size_t)b * NS * DIM);
        for (int idx = tid; idx < NS * DIM / 4; idx += 128) {
            float4 vv = qsrc[idx];
            int i = idx >> 7, d4 = idx & 127;
            qs[i][d4*4+0] = vv.x; qs[i][d4*4+1] = vv.y;
            qs[i][d4*4+2] = vv.z; qs[i][d4*4+3] = vv.w;
        }
        if (tid < NS) qb[tid] = qbk[b * NS + tid];
    }

    float acc[NS];
    const float* kbase = xn + (size_t)(b * NTOK + j0) * DIM;

    /* stage 1: dots (thread = token) */
    for (int dc = 0; dc < DIM; dc += 32) {
        __syncthreads();
        #pragma unroll
        for (int ii = 0; ii < 8; ii++) {
            int idx = tid + ii * 128;
            int r = idx >> 3, c4 = idx & 7;
            float4 vv = *(const float4*)(kbase + (size_t)r * DIM + dc + c4 * 4);
            *(float4*)&kch[r][c4 * 4] = vv;
        }
        __syncthreads();
        if (dc == 0) {
            #pragma unroll
            for (int i = 0; i < NS; i++) acc[i] = qb[i];
        }
        #pragma unroll
        for (int c4 = 0; c4 < 8; c4++) {
            float4 k4 = *(const float4*)&kch[tid][c4 * 4];
            #pragma unroll
            for (int i = 0; i < NS; i++) {
                float4 q4 = *(const float4*)&qs[i][dc + c4 * 4];
                acc[i] += k4.x*q4.x + k4.y*q4.y + k4.z*q4.z + k4.w*q4.w;
            }
        }
    }

    /* stage 2: softmax over slots; write transposed attn + rowsum partials */
    float m = -1e30f;
    #pragma unroll
    for (int i = 0; i < NS; i++) { acc[i] *= ATT_SCALE; m = fmaxf(m, acc[i]); }
    float sum = 0.f;
    #pragma unroll
    for (int i = 0; i < NS; i++) { acc[i] = expf(acc[i] - m); sum += acc[i]; }
    float inv = 1.0f / sum;
    int w = tid >> 5, l = tid & 31;
    #pragma unroll
    for (int i = 0; i < NS; i++) {
        float p = acc[i] * inv + ATT_EPS;
        as_t[tid][i] = p;
        float s = p;
        #pragma unroll
        for (int o = 16; o > 0; o >>= 1) s += __shfl_down_sync(0xffffffffu, s, o);
        if (l == 0) rsm[i][w] = s;
    }
    __syncthreads();
    if (tid < NS)
        prs[((size_t)b * 8 + blk) * NS + tid] = rsm[tid][0] + rsm[tid][1] + rsm[tid][2] + rsm[tid][3];

    /* stage 3: paw[i][c] = sum_j as_t[j][i]*xn[j,c].
       warp w -> cols 128w + 4l .. +3 (all 8 slots); xn via coalesced LDG. */
    float4 av[NS];
    #pragma unroll
    for (int i = 0; i < NS; i++) av[i] = make_float4(0.f, 0.f, 0.f, 0.f);
    const float* xrow = kbase + w * 128 + l * 4;
    #pragma unroll 4
    for (int j = 0; j < 128; j++) {
        float4 xv = *(const float4*)(xrow + (size_t)j * DIM);
        float4 a03 = *(const float4*)&as_t[j][0];
        float4 a47 = *(const float4*)&as_t[j][4];
        av[0].x += a03.x*xv.x; av[0].y += a03.x*xv.y; av[0].z += a03.x*xv.z; av[0].w += a03.x*xv.w;
        av[1].x += a03.y*xv.x; av[1].y += a03.y*xv.y; av[1].z += a03.y*xv.z; av[1].w += a03.y*xv.w;
        av[2].x += a03.z*xv.x; av[2].y += a03.z*xv.y; av[2].z += a03.z*xv.z; av[2].w += a03.z*xv.w;
        av[3].x += a03.w*xv.x; av[3].y += a03.w*xv.y; av[3].z += a03.w*xv.z; av[3].w += a03.w*xv.w;
        av[4].x += a47.x*xv.x; av[4].y += a47.x*xv.y; av[4].z += a47.x*xv.z; av[4].w += a47.x*xv.w;
        av[5].x += a47.y*xv.x; av[5].y += a47.y*xv.y; av[5].z += a47.y*xv.z; av[5].w += a47.y*xv.w;
        av[6].x += a47.z*xv.x; av[6].y += a47.z*xv.y; av[6].z += a47.z*xv.z; av[6].w += a47.z*xv.w;
        av[7].x += a47.w*xv.x; av[7].y += a47.w*xv.y; av[7].z += a47.w*xv.z; av[7].w += a47.w*xv.w;
    }
    int c = w * 128 + l * 4;
    #pragma unroll
    for (int i = 0; i < NS; i++)
        *(float4*)(paw + (((size_t)b * 8 + blk) * NS + i) * DIM + c) = av[i];
}

/* ---- reduce partials: awn[b,i,c] = rtf32( sum_blk paw / sum_blk prs ) ---- */
__global__ __launch_bounds__(512) void attn_reduce(const float* __restrict__ paw,
                                                   const float* __restrict__ prs,
                                                   float* __restrict__ awn) {
    int b = blockIdx.x;
    int c = threadIdx.x;
    __shared__ float rs[NS];
    if (c < NS) {
        float s = 0.f;
        #pragma unroll
        for (int blk = 0; blk < 8; blk++)
            s += prs[((size_t)b * 8 + blk) * NS + c];
        rs[c] = 1.0f / s;
    }
    __syncthreads();
    #pragma unroll
    for (int i = 0; i < NS; i++) {
        float s = 0.f;
        #pragma unroll
        for (int blk = 0; blk < 8; blk++)
            s += paw[(((size_t)b * 8 + blk) * NS + i) * DIM + c];
        awn[((size_t)b * NS + i) * DIM + c] = rtf32(s * rs[i]);
    }
}

/* ---- fused GRU gate + LayerNorm(ff) ---- */
__global__ __launch_bounds__(512) void gru_ln(const float* __restrict__ xg,
                                              const float* __restrict__ hg,
                                              float* __restrict__ slots,
                                              float* __restrict__ sbuf,
                                              const float* __restrict__ gamma,
                                              const float* __restrict__ beta) {
    int row = blockIdx.x;
    int c = threadIdx.x;
    size_t base = (size_t)row * 3 * DIM;
    float xr = xg[base + c],         hr = hg[base + c];
    float xz = xg[base + DIM + c],   hz = hg[base + DIM + c];
    float xn = xg[base + 2*DIM + c], hn = hg[base + 2*DIM + c];
    float r = 1.0f / (1.0f + expf(-(xr + hr)));
    float z = 1.0f / (1.0f + expf(-(xz + hz)));
    float n = tanhf(xn + r * hn);
    size_t si = (size_t)row * DIM + c;
    float prev = slots[si];
    float v = (1.0f - z) * n + z * prev;
    slots[si] = v;

    __shared__ float sh[32];
    float s = v, ss = v * v;
    #pragma unroll
    for (int o = 16; o > 0; o >>= 1) {
        s  += __shfl_down_sync(0xffffffffu, s,  o);
        ss += __shfl_down_sync(0xffffffffu, ss, o);
    }
    int w = c >> 5, l = c & 31;
    if (l == 0) { sh[w] = s; sh[16 + w] = ss; }
    __syncthreads();
    float ts = 0.f, tss = 0.f;
    #pragma unroll
    for (int i = 0; i < 16; i++) { ts += sh[i]; tss += sh[16 + i]; }
    float mean = ts * (1.0f / DIM);
    float var  = tss * (1.0f / DIM) - mean * mean;
    float rstd = rsqrtf(var + LN_EPS);
    sbuf[si] = rtf32((v - mean) * rstd * gamma[c] + beta[c]);
}

/* ---------------- host ---------------- */
static float* sym(const void* s) {
    void* p = nullptr;
    cudaGetSymbolAddress(&p, s);
    return (float*)p;
}

extern "C" void kernel_launch(void* const* d_in, const int* in_sizes, int n_in,
                              void* d_out, int out_size) {
    const float* inputs    = (const float*)d_in[0];
    const float* noise     = (const float*)d_in[1];
    const float* mu        = (const float*)d_in[2];
    const float* logsigma  = (const float*)d_in[3];
    const float* gi        = (const float*)d_in[4];
    const float* bei       = (const float*)d_in[5];
    const float* gsl       = (const float*)d_in[6];
    const float* besl      = (const float*)d_in[7];
    const float* gff       = (const float*)d_in[8];
    const float* beff      = (const float*)d_in[9];
    const float* Wq        = (const float*)d_in[10];
    const float* bq        = (const float*)d_in[11];
    const float* Wk        = (const float*)d_in[12];
    const float* bk        = (const float*)d_in[13];
    const float* Wv        = (const float*)d_in[14];
    const float* bv        = (const float*)d_in[15];
    const float* W_ih      = (const float*)d_in[16];
    const float* b_ih      = (const float*)d_in[17];
    const float* W_hh      = (const float*)d_in[18];
    const float* b_hh      = (const float*)d_in[19];
    const float* W1        = (const float*)d_in[20];
    const float* b1        = (const float*)d_in[21];
    const float* W2        = (const float*)d_in[22];
    const float* b2        = (const float*)d_in[23];
    float* slots = (float*)d_out;

    float* xn   = sym(g_xn);
    float* WkT  = sym(g_WkT);
    float* WqT  = sym(g_WqT);
    float* WvT  = sym(g_WvT);
    float* Wp   = sym(g_Wp);
    float* Wc   = sym(g_Wc);
    float* Wihr = sym(g_Wih_r);
    float* Whhr = sym(g_Whh_r);
    float* W1r  = sym(g_W1_r);
    float* W2r  = sym(g_W2_r);
    float* zero = sym(g_zero);
    float* vv   = sym(g_v);
    float* uu   = sym(g_u);
    float* c0   = sym(g_c0);
    float* bc   = sym(g_bc);
    float* sbuf = sym(g_s);
    float* srd  = sym(g_sr);
    float* qk   = sym(g_qk);
    float* qbk  = sym(g_qbk);
    float* paw  = sym(g_paw);
    float* prs  = sym(g_prs);
    float* awn  = sym(g_awn);
    float* xg   = sym(g_xg);
    float* hg   = sym(g_hg);
    float* hid  = sym(g_hid);

    cudaFuncSetAttribute(mma_gemm<0,0,0,0>, cudaFuncAttributeMaxDynamicSharedMemorySize, GSMEM);
    cudaFuncSetAttribute(mma_gemm<0,0,1,0>, cudaFuncAttributeMaxDynamicSharedMemorySize, GSMEM);
    cudaFuncSetAttribute(mma_gemm<1,0,1,0>, cudaFuncAttributeMaxDynamicSharedMemorySize, GSMEM);
    cudaFuncSetAttribute(mma_gemm<0,1,0,1>, cudaFuncAttributeMaxDynamicSharedMemorySize, GSMEM);
    cudaFuncSetAttribute(mma_gemm_dual,     cudaFuncAttributeMaxDynamicSharedMemorySize, GSMEM);

    /* ln_rows(inputs) is my launch #4 (ncu -s 5 -c 1 captures it) */
    init_slots<<<SROWS*DIM/256, 256>>>(noise, mu, logsigma, slots, srd, zero); /* 1 */
    rct_all<<<dim3(16,16,3), 256>>>(Wk, Wq, Wv, WkT, WqT, WvT);                /* 2 */
    rc_all<<<2097152/256, 256>>>(W_ih, W_hh, W1, W2, Wihr, Whhr, W1r, W2r);    /* 3 */
    ln_rows<<<NROWS, 128>>>(inputs, xn, gi, bei);                              /* 4 */
    mma_gemm<0,0,1,0><<<dim3(DIM/128, DIM/64), 256, GSMEM>>>(WkT, WqT, zero, Wp, nullptr, DIM, DIM, DIM);
    mma_gemm<0,0,1,0><<<dim3(DIM/128, 3*DIM/64), 256, GSMEM>>>(Wihr, WvT, zero, Wc, nullptr, 3*DIM, DIM, DIM);
    vec_fold<<<321, 256>>>(WkT, WqT, W_ih, bq, bk, bv, b_ih, vv, uu, bc, c0);

    for (int it = 0; it < 3; it++) {
        ln_rows_q<<<SROWS, 128>>>(slots, sbuf, gsl, besl, uu, c0, qbk);
        mma_gemm<0,0,0,0><<<dim3(DIM/128, SROWS/64), 256, GSMEM>>>(sbuf, Wp, vv, qk, nullptr, SROWS, DIM, DIM);
        attn_fused<<<dim3(8, BATCH), 128>>>(xn, qk, qbk, paw, prs);
        attn_reduce<<<BATCH, 512>>>(paw, prs, awn);
        mma_gemm_dual<<<dim3(3*DIM/128, SROWS/64, 2), 256, GSMEM>>>(
            awn, Wc, bc, xg, srd, Whhr, b_hh, hg, SROWS, 3*DIM, DIM);
        gru_ln<<<SROWS, 512>>>(xg, hg, slots, sbuf, gff, beff);
        mma_gemm<1,0,1,0><<<dim3(HIDN/128, SROWS/64), 256, GSMEM>>>(sbuf, W1r, b1, hid, nullptr, SROWS, HIDN, DIM);
        mma_gemm<0,1,0,1><<<dim3(DIM/128, SROWS/64), 256, GSMEM>>>(hid, W2r, b2, slots, srd, SROWS, DIM, HIDN);
    }
    (void)in_sizes; (void)n_in; (void)out_size;
}

// round 16
// speedup vs baseline: 1.4745x; 1.1059x over previous
#include <cuda_runtime.h>
#include <cuda_bf16.h>
#include <math.h>
#include <stdint.h>

#define DIM   512
#define NS    8
#define BATCH 128
#define NTOK  1024
#define HIDN  512
#define NROWS (BATCH*NTOK)   /* 131072 */
#define SROWS (BATCH*NS)     /* 1024   */
#define ATT_SCALE 0.04419417382415922f
#define LN_EPS 1e-5f
#define ATT_EPS 1e-8f

/* ---------------- scratch (device globals; no allocation) ---------------- */
__device__ __nv_bfloat16 g_xn[(size_t)NROWS*DIM];   /* bf16: attention-only */
__device__ float g_WkT[DIM*DIM];
__device__ float g_WqT[DIM*DIM];
__device__ float g_WvT[DIM*DIM];
__device__ float g_Wp[DIM*DIM];
__device__ float g_Wc[3*DIM*DIM];
__device__ float g_Wih_r[3*DIM*DIM];
__device__ float g_Whh_r[3*DIM*DIM];
__device__ float g_W1_r[HIDN*DIM];
__device__ float g_W2_r[DIM*HIDN];
__device__ float g_zero[DIM];
__device__ float g_v[DIM];
__device__ float g_u[DIM];
__device__ float g_c0[1];
__device__ float g_bc[3*DIM];
__device__ float g_s [SROWS*DIM];
__device__ float g_sr[SROWS*DIM];
__device__ float g_qk[SROWS*DIM];
__device__ float g_qbk[SROWS];
__device__ float g_paw[(size_t)BATCH*8*NS*DIM];   /* 16 MB */
__device__ float g_prs[BATCH*8*NS];
__device__ float g_awn[SROWS*DIM];
__device__ float g_xg[SROWS*3*DIM];
__device__ float g_hg[SROWS*3*DIM];
__device__ float g_hid[SROWS*HIDN];

/* ---------------- helpers ---------------- */
__device__ __forceinline__ float rtf32(float x) {
    uint32_t u; asm("cvt.rna.tf32.f32 %0, %1;" : "=r"(u) : "f"(x));
    return __uint_as_float(u);
}
__device__ __forceinline__ uint32_t s2u(const void* p) {
    uint32_t a;
    asm("{ .reg .u64 t; cvta.to.shared.u64 t, %1; cvt.u32.u64 %0, t; }" : "=r"(a) : "l"(p));
    return a;
}

#define CP16(dst, src) \
    asm volatile("cp.async.cg.shared.global [%0], [%1], 16;" :: "r"(dst), "l"(src))
#define CP_COMMIT() asm volatile("cp.async.commit_group;" ::: "memory")
#define CP_WAIT(n)  asm volatile("cp.async.wait_group %0;" :: "n"(n) : "memory")

#define MMA_TF32(d, a, b) \
    asm volatile("mma.sync.aligned.m16n8k8.row.col.f32.tf32.tf32.f32 " \
        "{%0,%1,%2,%3}, {%4,%5,%6,%7}, {%8,%9}, {%0,%1,%2,%3};" \
        : "+f"((d)[0]), "+f"((d)[1]), "+f"((d)[2]), "+f"((d)[3]) \
        : "r"(__float_as_uint((a)[0])), "r"(__float_as_uint((a)[1])), \
          "r"(__float_as_uint((a)[2])), "r"(__float_as_uint((a)[3])), \
          "r"(__float_as_uint((b)[0])), "r"(__float_as_uint((b)[1])))

/* ============ tf32 mma.sync GEMM (R13/R15 proven config) ============ */
#define ASTR 36
#define MT 2
#define STGF ((64 + 128) * ASTR)
#define GSMEM (STGF * 4 * 2)                 /* 55296 bytes */

template<int RELU, int ADDC, int RND, int RC>
__device__ __forceinline__ void gemm_body(const float* __restrict__ A,
                                          const float* __restrict__ W,
                                          const float* __restrict__ bias,
                                          float* __restrict__ C,
                                          float* __restrict__ Caux,
                                          int M, int N, int K) {
    extern __shared__ float smem[];
    int tid = threadIdx.x;
    int lane = tid & 31, wid = tid >> 5;
    int wm = wid & 1, wn = wid >> 1;
    int m0 = blockIdx.y * 64, n0 = blockIdx.x * 128;
    int r0 = lane >> 2, k4 = lane & 3;

    float acc[MT][4][4];
    #pragma unroll
    for (int mt = 0; mt < MT; mt++)
        #pragma unroll
        for (int nt = 0; nt < 4; nt++)
            #pragma unroll
            for (int i = 0; i < 4; i++) acc[mt][nt][i] = 0.f;

    const int KT = K >> 5;

    auto load_stage = [&](int kt, int s) {
        const float* Ag = A + (size_t)m0 * K + (kt << 5);
        const float* Wg = W + (size_t)n0 * K + (kt << 5);
        float* Ab = smem + s * STGF;
        float* Bb = Ab + 64 * ASTR;
        #pragma unroll
        for (int i = 0; i < MT; i++) {
            int idx = tid + (i << 8);
            int r = idx >> 3, c4 = (idx & 7) << 2;
            CP16(s2u(Ab + r * ASTR + c4), Ag + (size_t)r * K + c4);
        }
        #pragma unroll
        for (int i = 0; i < 4; i++) {
            int idx = tid + (i << 8);
            int r = idx >> 3, c4 = (idx & 7) << 2;
            CP16(s2u(Bb + r * ASTR + c4), Wg + (size_t)r * K + c4);
        }
    };

    load_stage(0, 0); CP_COMMIT();

    for (int kt = 0; kt < KT; kt++) {
        int s = kt & 1;
        if (kt + 1 < KT) { load_stage(kt + 1, s ^ 1); CP_COMMIT(); CP_WAIT(1); }
        else             { CP_WAIT(0); }
        __syncthreads();

        const float* Ab = smem + s * STGF + (wm * 32 + r0) * ASTR + k4;
        const float* Bb = smem + s * STGF + 64 * ASTR + (wn * 32 + r0) * ASTR + k4;
        #pragma unroll
        for (int ks = 0; ks < 4; ks++) {
            int kb = ks << 3;
            float af[MT][4], bf[4][2];
            #pragma unroll
            for (int mt = 0; mt < MT; mt++) {
                af[mt][0] = Ab[(mt * 16    ) * ASTR + kb];
                af[mt][1] = Ab[(mt * 16 + 8) * ASTR + kb];
                af[mt][2] = Ab[(mt * 16    ) * ASTR + kb + 4];
                af[mt][3] = Ab[(mt * 16 + 8) * ASTR + kb + 4];
            }
            #pragma unroll
            for (int nt = 0; nt < 4; nt++) {
                bf[nt][0] = Bb[nt * 8 * ASTR + kb];
                bf[nt][1] = Bb[nt * 8 * ASTR + kb + 4];
            }
            #pragma unroll
            for (int mt = 0; mt < MT; mt++)
                #pragma unroll
                for (int nt = 0; nt < 4; nt++)
                    MMA_TF32(acc[mt][nt], af[mt], bf[nt]);
        }
        __syncthreads();
    }

    #pragma unroll
    for (int mt = 0; mt < MT; mt++) {
        int mg = m0 + wm * 32 + mt * 16 + r0;
        #pragma unroll
        for (int nt = 0; nt < 4; nt++) {
            int ng = n0 + wn * 32 + nt * 8 + (k4 << 1);
            float b0 = bias[ng], b1 = bias[ng + 1];
            float* c0p = C + (size_t)mg * N + ng;
            float* c1p = C + (size_t)(mg + 8) * N + ng;
            float o0 = acc[mt][nt][0] + b0, o1 = acc[mt][nt][1] + b1;
            float o2 = acc[mt][nt][2] + b0, o3 = acc[mt][nt][3] + b1;
            if (RELU) {
                o0 = fmaxf(o0, 0.f); o1 = fmaxf(o1, 0.f);
                o2 = fmaxf(o2, 0.f); o3 = fmaxf(o3, 0.f);
            }
            if (ADDC) {
                float2 e0 = *(const float2*)c0p;
                float2 e1 = *(const float2*)c1p;
                o0 += e0.x; o1 += e0.y; o2 += e1.x; o3 += e1.y;
            }
            if (RND) { o0 = rtf32(o0); o1 = rtf32(o1); o2 = rtf32(o2); o3 = rtf32(o3); }
            *(float2*)c0p = make_float2(o0, o1);
            *(float2*)c1p = make_float2(o2, o3);
            if (RC) {
                float* a0p = Caux + (size_t)mg * N + ng;
                float* a1p = Caux + (size_t)(mg + 8) * N + ng;
                *(float2*)a0p = make_float2(rtf32(o0), rtf32(o1));
                *(float2*)a1p = make_float2(rtf32(o2), rtf32(o3));
            }
        }
    }
}

template<int RELU, int ADDC, int RND, int RC>
__global__ __launch_bounds__(256, 3) void mma_gemm(const float* __restrict__ A,
                                                   const float* __restrict__ W,
                                                   const float* __restrict__ bias,
                                                   float* __restrict__ C,
                                                   float* __restrict__ Caux,
                                                   int M, int N, int K) {
    gemm_body<RELU, ADDC, RND, RC>(A, W, bias, C, Caux, M, N, K);
}

__global__ __launch_bounds__(256, 3) void mma_gemm_dual(const float* __restrict__ A0,
                                                        const float* __restrict__ W0,
                                                        const float* __restrict__ b0,
                                                        float* __restrict__ C0,
                                                        const float* __restrict__ A1,
                                                        const float* __restrict__ W1,
                                                        const float* __restrict__ b1,
                                                        float* __restrict__ C1,
                                                        int M, int N, int K) {
    if (blockIdx.z == 0) gemm_body<0, 0, 0, 0>(A0, W0, b0, C0, nullptr, M, N, K);
    else                 gemm_body<0, 0, 0, 0>(A1, W1, b1, C1, nullptr, M, N, K);
}

/* ------- slot init: slots + rounded copy; zero bias buffer ------- */
__global__ void init_slots(const float* __restrict__ noise,
                           const float* __restrict__ mu,
                           const float* __restrict__ logsigma,
                           float* __restrict__ slots,
                           float* __restrict__ srd,
                           float* __restrict__ zero) {
    int idx = blockIdx.x * blockDim.x + threadIdx.x;
    int d = idx & (DIM - 1);
    float v = mu[d] + expf(logsigma[d]) * noise[idx];
    slots[idx] = v;
    srd[idx] = rtf32(v);
    if (idx < DIM) zero[idx] = 0.f;
}

/* ---- merged round-copy of all 4 plain weights ---- */
__global__ void rc_all(const float* __restrict__ Wih, const float* __restrict__ Whh,
                       const float* __restrict__ W1,  const float* __restrict__ W2,
                       float* __restrict__ Wihr, float* __restrict__ Whhr,
                       float* __restrict__ W1r,  float* __restrict__ W2r) {
    int i = blockIdx.x * 256 + threadIdx.x;
    const float* s; float* d; int off;
    if (i < 786432)        { s = Wih; d = Wihr; off = i; }
    else if (i < 1572864)  { s = Whh; d = Whhr; off = i - 786432; }
    else if (i < 1835008)  { s = W1;  d = W1r;  off = i - 1572864; }
    else                   { s = W2;  d = W2r;  off = i - 1835008; }
    d[off] = rtf32(s[off]);
}

/* ---- merged transposed round-copy (z selects Wk/Wq/Wv) ---- */
__global__ void rct_all(const float* __restrict__ Wk, const float* __restrict__ Wq,
                        const float* __restrict__ Wv,
                        float* __restrict__ WkT, float* __restrict__ WqT,
                        float* __restrict__ WvT) {
    __shared__ float tile[32][33];
    const float* src = (blockIdx.z == 0) ? Wk : (blockIdx.z == 1) ? Wq : Wv;
    float* dst       = (blockIdx.z == 0) ? WkT : (blockIdx.z == 1) ? WqT : WvT;
    int c0 = blockIdx.x * 32, d0 = blockIdx.y * 32;
    int tx = threadIdx.x & 31, ty = threadIdx.x >> 5;
    #pragma unroll
    for (int i = 0; i < 32; i += 8)
        tile[ty + i][tx] = src[(size_t)(d0 + ty + i) * DIM + c0 + tx];
    __syncthreads();
    #pragma unroll
    for (int i = 0; i < 32; i += 8)
        dst[(size_t)(c0 + ty + i) * DIM + d0 + tx] = rtf32(tile[tx][ty + i]);
}

/* ---- vec_fold: v = bq@Wk, u = bk@Wq, bc = bv@W_ih^T + b_ih, c0 = bq·bk ---- */
__global__ __launch_bounds__(256) void vec_fold(const float* __restrict__ WkT,
                                                const float* __restrict__ WqT,
                                                const float* __restrict__ W_ih,
                                                const float* __restrict__ bq,
                                                const float* __restrict__ bk,
                                                const float* __restrict__ bv,
                                                const float* __restrict__ b_ih,
                                                float* __restrict__ v,
                                                float* __restrict__ u,
                                                float* __restrict__ bc,
                                                float* __restrict__ c0) {
    int gw = blockIdx.x * 8 + (threadIdx.x >> 5);
    int l = threadIdx.x & 31;
    if (gw >= 2561) return;
    const float* row; const float* vec;
    if (gw < 512)       { row = WkT + (size_t)gw * DIM;          vec = bq; }
    else if (gw < 1024) { row = WqT + (size_t)(gw - 512) * DIM;  vec = bk; }
    else if (gw < 2560) { row = W_ih + (size_t)(gw - 1024) * DIM; vec = bv; }
    else                { row = bq;                               vec = bk; }
    float s = 0.f;
    for (int c = l; c < DIM; c += 32) s += row[c] * vec[c];
    #pragma unroll
    for (int o = 16; o > 0; o >>= 1) s += __shfl_down_sync(0xffffffffu, s, o);
    if (l == 0) {
        if (gw < 512) v[gw] = s;
        else if (gw < 1024) u[gw - 512] = s;
        else if (gw < 2560) bc[gw - 1024] = s + b_ih[gw - 1024];
        else c0[0] = s;
    }
}

/* ---- input LayerNorm: writes bf16 xn (attention-only consumer) ---- */
__global__ void ln_rows_bf(const float* __restrict__ in, __nv_bfloat16* __restrict__ out,
                           const float* __restrict__ gamma, const float* __restrict__ beta) {
    int row = blockIdx.x;
    int t = threadIdx.x;
    const float4* ip = (const float4*)(in + (size_t)row * DIM);
    float4 x = ip[t];
    float s  = x.x + x.y + x.z + x.w;
    float ss = x.x*x.x + x.y*x.y + x.z*x.z + x.w*x.w;
    #pragma unroll
    for (int o = 16; o > 0; o >>= 1) {
        s  += __shfl_down_sync(0xffffffffu, s,  o);
        ss += __shfl_down_sync(0xffffffffu, ss, o);
    }
    __shared__ float sh[8];
    int w = t >> 5, l = t & 31;
    if (l == 0) { sh[w] = s; sh[4 + w] = ss; }
    __syncthreads();
    s  = sh[0] + sh[1] + sh[2] + sh[3];
    ss = sh[4] + sh[5] + sh[6] + sh[7];
    float mean = s * (1.0f / DIM);
    float var  = ss * (1.0f / DIM) - mean * mean;
    float rstd = rsqrtf(var + LN_EPS);
    float4 g = ((const float4*)gamma)[t];
    float4 b = ((const float4*)beta)[t];
    __nv_bfloat162 h0 = __floats2bfloat162_rn((x.x - mean) * rstd * g.x + b.x,
                                              (x.y - mean) * rstd * g.y + b.y);
    __nv_bfloat162 h1 = __floats2bfloat162_rn((x.z - mean) * rstd * g.z + b.z,
                                              (x.w - mean) * rstd * g.w + b.w);
    uint2 pk;
    pk.x = *(uint32_t*)&h0;
    pk.y = *(uint32_t*)&h1;
    *(uint2*)(out + (size_t)row * DIM + 4 * t) = pk;
}

/* ---- slot LayerNorm + fused qbk = out·u + c0 (fp32, feeds GEMM) ---- */
__global__ void ln_rows_q(const float* __restrict__ in, float* __restrict__ out,
                          const float* __restrict__ gamma, const float* __restrict__ beta,
                          const float* __restrict__ u, const float* __restrict__ c0,
                          float* __restrict__ qbk) {
    int row = blockIdx.x;
    int t = threadIdx.x;
    const float4* ip = (const float4*)(in + (size_t)row * DIM);
    float4 x = ip[t];
    float s  = x.x + x.y + x.z + x.w;
    float ss = x.x*x.x + x.y*x.y + x.z*x.z + x.w*x.w;
    #pragma unroll
    for (int o = 16; o > 0; o >>= 1) {
        s  += __shfl_down_sync(0xffffffffu, s,  o);
        ss += __shfl_down_sync(0xffffffffu, ss, o);
    }
    __shared__ float sh[8];
    __shared__ float sh2[4];
    int w = t >> 5, l = t & 31;
    if (l == 0) { sh[w] = s; sh[4 + w] = ss; }
    __syncthreads();
    s  = sh[0] + sh[1] + sh[2] + sh[3];
    ss = sh[4] + sh[5] + sh[6] + sh[7];
    float mean = s * (1.0f / DIM);
    float var  = ss * (1.0f / DIM) - mean * mean;
    float rstd = rsqrtf(var + LN_EPS);
    float4 g = ((const float4*)gamma)[t];
    float4 b = ((const float4*)beta)[t];
    float4 o4;
    o4.x = rtf32((x.x - mean) * rstd * g.x + b.x);
    o4.y = rtf32((x.y - mean) * rstd * g.y + b.y);
    o4.z = rtf32((x.z - mean) * rstd * g.z + b.z);
    o4.w = rtf32((x.w - mean) * rstd * g.w + b.w);
    ((float4*)(out + (size_t)row * DIM))[t] = o4;
    float4 uv = ((const float4*)u)[t];
    float sv = o4.x*uv.x + o4.y*uv.y + o4.z*uv.z + o4.w*uv.w;
    #pragma unroll
    for (int o = 16; o > 0; o >>= 1) sv += __shfl_down_sync(0xffffffffu, sv, o);
    if (l == 0) sh2[w] = sv;
    __syncthreads();
    if (t == 0) qbk[row] = sh2[0] + sh2[1] + sh2[2] + sh2[3] + c0[0];
}

/* ==== fused attention (bf16 xn): dots + softmax + partial V-contraction ==== */
#define KSTR 36
__global__ __launch_bounds__(128) void attn_fused(const __nv_bfloat16* __restrict__ xn,
                                                  const float* __restrict__ qkmat,
                                                  const float* __restrict__ qbk,
                                                  float* __restrict__ paw,
                                                  float* __restrict__ prs) {
    int b = blockIdx.y, blk = blockIdx.x;
    int j0 = blk * 128;
    int tid = threadIdx.x;
    __shared__ __align__(16) float qs[NS][DIM];      /* 16 KB */
    __shared__ __align__(16) float kch[128][KSTR];   /* 18 KB */
    __shared__ __align__(16) float as_t[128][12];    /* 6 KB */
    __shared__ float qb[NS];
    __shared__ float rsm[NS][4];

    {
        const float4* qsrc = (const float4*)(qkmat + (size_t)b * NS * DIM);
        for (int idx = tid; idx < NS * DIM / 4; idx += 128) {
            float4 vv = qsrc[idx];
            int i = idx >> 7, d4 = idx & 127;
            qs[i][d4*4+0] = vv.x; qs[i][d4*4+1] = vv.y;
            qs[i][d4*4+2] = vv.z; qs[i][d4*4+3] = vv.w;
        }
        if (tid < NS) qb[tid] = qbk[b * NS + tid];
    }

    float acc[NS];
    const __nv_bfloat16* kbase = xn + (size_t)(b * NTOK + j0) * DIM;

    /* stage 1: dots; staging converts bf16 -> fp32 in kch */
    for (int dc = 0; dc < DIM; dc += 32) {
        __syncthreads();
        /* 128 rows x 32 bf16 = 512 segs of 8 bf16 (16 B) */
        #pragma unroll
        for (int ii = 0; ii < 4; ii++) {
            int idx = tid + ii * 128;
            int r = idx >> 2, cseg = idx & 3;         /* cseg: 8 bf16 each */
            uint4 raw = *(const uint4*)(kbase + (size_t)r * DIM + dc + cseg * 8);
            const __nv_bfloat162* hp = (const __nv_bfloat162*)&raw;
            float2 f0 = __bfloat1622float2(hp[0]);
            float2 f1 = __bfloat1622float2(hp[1]);
            float2 f2 = __bfloat1622float2(hp[2]);
            float2 f3 = __bfloat1622float2(hp[3]);
            float4* kp = (float4*)&kch[r][cseg * 8];
            kp[0] = make_float4(f0.x, f0.y, f1.x, f1.y);
            kp[1] = make_float4(f2.x, f2.y, f3.x, f3.y);
        }
        __syncthreads();
        if (dc == 0) {
            #pragma unroll
            for (int i = 0; i < NS; i++) acc[i] = qb[i];
        }
        #pragma unroll
        for (int c4 = 0; c4 < 8; c4++) {
            float4 k4 = *(const float4*)&kch[tid][c4 * 4];
            #pragma unroll
            for (int i = 0; i < NS; i++) {
                float4 q4 = *(const float4*)&qs[i][dc + c4 * 4];
                acc[i] += k4.x*q4.x + k4.y*q4.y + k4.z*q4.z + k4.w*q4.w;
            }
        }
    }

    /* stage 2: softmax over slots; transposed attn + rowsum partials */
    float m = -1e30f;
    #pragma unroll
    for (int i = 0; i < NS; i++) { acc[i] *= ATT_SCALE; m = fmaxf(m, acc[i]); }
    float sum = 0.f;
    #pragma unroll
    for (int i = 0; i < NS; i++) { acc[i] = expf(acc[i] - m); sum += acc[i]; }
    float inv = 1.0f / sum;
    int w = tid >> 5, l = tid & 31;
    #pragma unroll
    for (int i = 0; i < NS; i++) {
        float p = acc[i] * inv + ATT_EPS;
        as_t[tid][i] = p;
        float s = p;
        #pragma unroll
        for (int o = 16; o > 0; o >>= 1) s += __shfl_down_sync(0xffffffffu, s, o);
        if (l == 0) rsm[i][w] = s;
    }
    __syncthreads();
    if (tid < NS)
        prs[((size_t)b * 8 + blk) * NS + tid] = rsm[tid][0] + rsm[tid][1] + rsm[tid][2] + rsm[tid][3];

    /* stage 3: warp w -> cols 128w+4l..+3; bf16 LDG.64 (L2-hot), attn broadcast */
    float4 av[NS];
    #pragma unroll
    for (int i = 0; i < NS; i++) av[i] = make_float4(0.f, 0.f, 0.f, 0.f);
    const __nv_bfloat16* xrow = kbase + w * 128 + l * 4;
    #pragma unroll 4
    for (int j = 0; j < 128; j++) {
        uint2 raw = *(const uint2*)(xrow + (size_t)j * DIM);
        const __nv_bfloat162* hp = (const __nv_bfloat162*)&raw;
        float2 f0 = __bfloat1622float2(hp[0]);
        float2 f1 = __bfloat1622float2(hp[1]);
        float4 xv = make_float4(f0.x, f0.y, f1.x, f1.y);
        float4 a03 = *(const float4*)&as_t[j][0];
        float4 a47 = *(const float4*)&as_t[j][4];
        av[0].x += a03.x*xv.x; av[0].y += a03.x*xv.y; av[0].z += a03.x*xv.z; av[0].w += a03.x*xv.w;
        av[1].x += a03.y*xv.x; av[1].y += a03.y*xv.y; av[1].z += a03.y*xv.z; av[1].w += a03.y*xv.w;
        av[2].x += a03.z*xv.x; av[2].y += a03.z*xv.y; av[2].z += a03.z*xv.z; av[2].w += a03.z*xv.w;
        av[3].x += a03.w*xv.x; av[3].y += a03.w*xv.y; av[3].z += a03.w*xv.z; av[3].w += a03.w*xv.w;
        av[4].x += a47.x*xv.x; av[4].y += a47.x*xv.y; av[4].z += a47.x*xv.z; av[4].w += a47.x*xv.w;
        av[5].x += a47.y*xv.x; av[5].y += a47.y*xv.y; av[5].z += a47.y*xv.z; av[5].w += a47.y*xv.w;
        av[6].x += a47.z*xv.x; av[6].y += a47.z*xv.y; av[6].z += a47.z*xv.z; av[6].w += a47.z*xv.w;
        av[7].x += a47.w*xv.x; av[7].y += a47.w*xv.y; av[7].z += a47.w*xv.z; av[7].w += a47.w*xv.w;
    }
    int c = w * 128 + l * 4;
    #pragma unroll
    for (int i = 0; i < NS; i++)
        *(float4*)(paw + (((size_t)b * 8 + blk) * NS + i) * DIM + c) = av[i];
}

/* ---- reduce partials: awn[b,i,c] = rtf32( sum_blk paw / sum_blk prs ) ---- */
__global__ __launch_bounds__(512) void attn_reduce(const float* __restrict__ paw,
                                                   const float* __restrict__ prs,
                                                   float* __restrict__ awn) {
    int b = blockIdx.x;
    int c = threadIdx.x;
    __shared__ float rs[NS];
    if (c < NS) {
        float s = 0.f;
        #pragma unroll
        for (int blk = 0; blk < 8; blk++)
            s += prs[((size_t)b * 8 + blk) * NS + c];
        rs[c] = 1.0f / s;
    }
    __syncthreads();
    #pragma unroll
    for (int i = 0; i < NS; i++) {
        float s = 0.f;
        #pragma unroll
        for (int blk = 0; blk < 8; blk++)
            s += paw[(((size_t)b * 8 + blk) * NS + i) * DIM + c];
        awn[((size_t)b * NS + i) * DIM + c] = rtf32(s * rs[i]);
    }
}

/* ---- fused GRU gate + LayerNorm(ff) ---- */
__global__ __launch_bounds__(512) void gru_ln(const float* __restrict__ xg,
                                              const float* __restrict__ hg,
                                              float* __restrict__ slots,
                                              float* __restrict__ sbuf,
                                              const float* __restrict__ gamma,
                                              const float* __restrict__ beta) {
    int row = blockIdx.x;
    int c = threadIdx.x;
    size_t base = (size_t)row * 3 * DIM;
    float xr = xg[base + c],         hr = hg[base + c];
    float xz = xg[base + DIM + c],   hz = hg[base + DIM + c];
    float xn = xg[base + 2*DIM + c], hn = hg[base + 2*DIM + c];
    float r = 1.0f / (1.0f + expf(-(xr + hr)));
    float z = 1.0f / (1.0f + expf(-(xz + hz)));
    float n = tanhf(xn + r * hn);
    size_t si = (size_t)row * DIM + c;
    float prev = slots[si];
    float v = (1.0f - z) * n + z * prev;
    slots[si] = v;

    __shared__ float sh[32];
    float s = v, ss = v * v;
    #pragma unroll
    for (int o = 16; o > 0; o >>= 1) {
        s  += __shfl_down_sync(0xffffffffu, s,  o);
        ss += __shfl_down_sync(0xffffffffu, ss, o);
    }
    int w = c >> 5, l = c & 31;
    if (l == 0) { sh[w] = s; sh[16 + w] = ss; }
    __syncthreads();
    float ts = 0.f, tss = 0.f;
    #pragma unroll
    for (int i = 0; i < 16; i++) { ts += sh[i]; tss += sh[16 + i]; }
    float mean = ts * (1.0f / DIM);
    float var  = tss * (1.0f / DIM) - mean * mean;
    float rstd = rsqrtf(var + LN_EPS);
    sbuf[si] = rtf32((v - mean) * rstd * gamma[c] + beta[c]);
}

/* ---------------- host ---------------- */
static void* symv(const void* s) {
    void* p = nullptr;
    cudaGetSymbolAddress(&p, s);
    return p;
}

extern "C" void kernel_launch(void* const* d_in, const int* in_sizes, int n_in,
                              void* d_out, int out_size) {
    const float* inputs    = (const float*)d_in[0];
    const float* noise     = (const float*)d_in[1];
    const float* mu        = (const float*)d_in[2];
    const float* logsigma  = (const float*)d_in[3];
    const float* gi        = (const float*)d_in[4];
    const float* bei       = (const float*)d_in[5];
    const float* gsl       = (const float*)d_in[6];
    const float* besl      = (const float*)d_in[7];
    const float* gff       = (const float*)d_in[8];
    const float* beff      = (const float*)d_in[9];
    const float* Wq        = (const float*)d_in[10];
    const float* bq        = (const float*)d_in[11];
    const float* Wk        = (const float*)d_in[12];
    const float* bk        = (const float*)d_in[13];
    const float* Wv        = (const float*)d_in[14];
    const float* bv        = (const float*)d_in[15];
    const float* W_ih      = (const float*)d_in[16];
    const float* b_ih      = (const float*)d_in[17];
    const float* W_hh      = (const float*)d_in[18];
    const float* b_hh      = (const float*)d_in[19];
    const float* W1        = (const float*)d_in[20];
    const float* b1        = (const float*)d_in[21];
    const float* W2        = (const float*)d_in[22];
    const float* b2        = (const float*)d_in[23];
    float* slots = (float*)d_out;

    __nv_bfloat16* xn = (__nv_bfloat16*)symv(g_xn);
    float* WkT  = (float*)symv(g_WkT);
    float* WqT  = (float*)symv(g_WqT);
    float* WvT  = (float*)symv(g_WvT);
    float* Wp   = (float*)symv(g_Wp);
    float* Wc   = (float*)symv(g_Wc);
    float* Wihr = (float*)symv(g_Wih_r);
    float* Whhr = (float*)symv(g_Whh_r);
    float* W1r  = (float*)symv(g_W1_r);
    float* W2r  = (float*)symv(g_W2_r);
    float* zero = (float*)symv(g_zero);
    float* vv   = (float*)symv(g_v);
    float* uu   = (float*)symv(g_u);
    float* c0   = (float*)symv(g_c0);
    float* bc   = (float*)symv(g_bc);
    float* sbuf = (float*)symv(g_s);
    float* srd  = (float*)symv(g_sr);
    float* qk   = (float*)symv(g_qk);
    float* qbk  = (float*)symv(g_qbk);
    float* paw  = (float*)symv(g_paw);
    float* prs  = (float*)symv(g_prs);
    float* awn  = (float*)symv(g_awn);
    float* xg   = (float*)symv(g_xg);
    float* hg   = (float*)symv(g_hg);
    float* hid  = (float*)symv(g_hid);

    cudaFuncSetAttribute(mma_gemm<0,0,0,0>, cudaFuncAttributeMaxDynamicSharedMemorySize, GSMEM);
    cudaFuncSetAttribute(mma_gemm<0,0,1,0>, cudaFuncAttributeMaxDynamicSharedMemorySize, GSMEM);
    cudaFuncSetAttribute(mma_gemm<1,0,1,0>, cudaFuncAttributeMaxDynamicSharedMemorySize, GSMEM);
    cudaFuncSetAttribute(mma_gemm<0,1,0,1>, cudaFuncAttributeMaxDynamicSharedMemorySize, GSMEM);
    cudaFuncSetAttribute(mma_gemm_dual,     cudaFuncAttributeMaxDynamicSharedMemorySize, GSMEM);

    /* ln_rows_bf(inputs) is my launch #4 (ncu -s 5 -c 1 captures it) */
    init_slots<<<SROWS*DIM/256, 256>>>(noise, mu, logsigma, slots, srd, zero); /* 1 */
    rct_all<<<dim3(16,16,3), 256>>>(Wk, Wq, Wv, WkT, WqT, WvT);                /* 2 */
    rc_all<<<2097152/256, 256>>>(W_ih, W_hh, W1, W2, Wihr, Whhr, W1r, W2r);    /* 3 */
    ln_rows_bf<<<NROWS, 128>>>(inputs, xn, gi, bei);                           /* 4 */
    mma_gemm<0,0,1,0><<<dim3(DIM/128, DIM/64), 256, GSMEM>>>(WkT, WqT, zero, Wp, nullptr, DIM, DIM, DIM);
    mma_gemm<0,0,1,0><<<dim3(DIM/128, 3*DIM/64), 256, GSMEM>>>(Wihr, WvT, zero, Wc, nullptr, 3*DIM, DIM, DIM);
    vec_fold<<<321, 256>>>(WkT, WqT, W_ih, bq, bk, bv, b_ih, vv, uu, bc, c0);

    for (int it = 0; it < 3; it++) {
        ln_rows_q<<<SROWS, 128>>>(slots, sbuf, gsl, besl, uu, c0, qbk);
        mma_gemm<0,0,0,0><<<dim3(DIM/128, SROWS/64), 256, GSMEM>>>(sbuf, Wp, vv, qk, nullptr, SROWS, DIM, DIM);
        attn_fused<<<dim3(8, BATCH), 128>>>(xn, qk, qbk, paw, prs);
        attn_reduce<<<BATCH, 512>>>(paw, prs, awn);
        mma_gemm_dual<<<dim3(3*DIM/128, SROWS/64, 2), 256, GSMEM>>>(
            awn, Wc, bc, xg, srd, Whhr, b_hh, hg, SROWS, 3*DIM, DIM);
        gru_ln<<<SROWS, 512>>>(xg, hg, slots, sbuf, gff, beff);
        mma_gemm<1,0,1,0><<<dim3(HIDN/128, SROWS/64), 256, GSMEM>>>(sbuf, W1r, b1, hid, nullptr, SROWS, HIDN, DIM);
        mma_gemm<0,1,0,1><<<dim3(DIM/128, SROWS/64), 256, GSMEM>>>(hid, W2r, b2, slots, srd, SROWS, DIM, HIDN);
    }
    (void)in_sizes; (void)n_in; (void)out_size;
}

// round 17
// speedup vs baseline: 1.5035x; 1.0197x over previous
#include <cuda_runtime.h>
#include <cuda_bf16.h>
#include <math.h>
#include <stdint.h>

#define DIM   512
#define NS    8
#define BATCH 128
#define NTOK  1024
#define HIDN  512
#define NROWS (BATCH*NTOK)   /* 131072 */
#define SROWS (BATCH*NS)     /* 1024   */
#define ATT_SCALE 0.04419417382415922f
#define LN_EPS 1e-5f
#define ATT_EPS 1e-8f

/* ---------------- scratch (device globals; no allocation) ---------------- */
__device__ __nv_bfloat16 g_xn[(size_t)NROWS*DIM];   /* bf16: attention-only */
__device__ float g_WkT[DIM*DIM];
__device__ float g_WqT[DIM*DIM];
__device__ float g_WvT[DIM*DIM];
__device__ float g_Wp[DIM*DIM];
__device__ float g_Wc[3*DIM*DIM];
__device__ float g_Wih_r[3*DIM*DIM];
__device__ float g_Whh_r[3*DIM*DIM];
__device__ float g_W1_r[HIDN*DIM];
__device__ float g_W2_r[DIM*HIDN];
__device__ float g_zero[DIM];
__device__ float g_v[DIM];
__device__ float g_u[DIM];
__device__ float g_c0[1];
__device__ float g_bc[3*DIM];
__device__ float g_s [SROWS*DIM];
__device__ float g_sr[SROWS*DIM];
__device__ float g_qk[SROWS*DIM];
__device__ float g_qbk[SROWS];
__device__ float g_paw[(size_t)BATCH*8*NS*DIM];   /* 16 MB */
__device__ float g_prs[BATCH*8*NS];
__device__ float g_awn[SROWS*DIM];
__device__ float g_xg[SROWS*3*DIM];
__device__ float g_hg[SROWS*3*DIM];
__device__ float g_hid[SROWS*HIDN];

/* ---------------- helpers ---------------- */
__device__ __forceinline__ float rtf32(float x) {
    uint32_t u; asm("cvt.rna.tf32.f32 %0, %1;" : "=r"(u) : "f"(x));
    return __uint_as_float(u);
}
__device__ __forceinline__ uint32_t s2u(const void* p) {
    uint32_t a;
    asm("{ .reg .u64 t; cvta.to.shared.u64 t, %1; cvt.u32.u64 %0, t; }" : "=r"(a) : "l"(p));
    return a;
}

#define CP16(dst, src) \
    asm volatile("cp.async.cg.shared.global [%0], [%1], 16;" :: "r"(dst), "l"(src))
#define CP_COMMIT() asm volatile("cp.async.commit_group;" ::: "memory")
#define CP_WAIT(n)  asm volatile("cp.async.wait_group %0;" :: "n"(n) : "memory")

#define MMA_TF32(d, a, b) \
    asm volatile("mma.sync.aligned.m16n8k8.row.col.f32.tf32.tf32.f32 " \
        "{%0,%1,%2,%3}, {%4,%5,%6,%7}, {%8,%9}, {%0,%1,%2,%3};" \
        : "+f"((d)[0]), "+f"((d)[1]), "+f"((d)[2]), "+f"((d)[3]) \
        : "r"(__float_as_uint((a)[0])), "r"(__float_as_uint((a)[1])), \
          "r"(__float_as_uint((a)[2])), "r"(__float_as_uint((a)[3])), \
          "r"(__float_as_uint((b)[0])), "r"(__float_as_uint((b)[1])))

/* ============ tf32 mma.sync GEMM: 4-stage cp.async pipeline ============
   BM=64, BN=128, BK=32, 256 threads, wait_group(2) -> ~3 k-iters of latency
   in flight. smem 110.6 KB -> 2 CTAs/SM (fine: loop grids are ~1 wave). */
#define ASTR 36
#define MT 2
#define STGF ((64 + 128) * ASTR)
#define NSTG 4
#define GSMEM (STGF * 4 * NSTG)              /* 110592 bytes */

template<int RELU, int ADDC, int RND, int RC>
__device__ __forceinline__ void gemm_body(const float* __restrict__ A,
                                          const float* __restrict__ W,
                                          const float* __restrict__ bias,
                                          float* __restrict__ C,
                                          float* __restrict__ Caux,
                                          int M, int N, int K) {
    extern __shared__ float smem[];
    int tid = threadIdx.x;
    int lane = tid & 31, wid = tid >> 5;
    int wm = wid & 1, wn = wid >> 1;
    int m0 = blockIdx.y * 64, n0 = blockIdx.x * 128;
    int r0 = lane >> 2, k4 = lane & 3;

    float acc[MT][4][4];
    #pragma unroll
    for (int mt = 0; mt < MT; mt++)
        #pragma unroll
        for (int nt = 0; nt < 4; nt++)
            #pragma unroll
            for (int i = 0; i < 4; i++) acc[mt][nt][i] = 0.f;

    const int KT = K >> 5;

    auto load_stage = [&](int kt, int s) {
        const float* Ag = A + (size_t)m0 * K + (kt << 5);
        const float* Wg = W + (size_t)n0 * K + (kt << 5);
        float* Ab = smem + s * STGF;
        float* Bb = Ab + 64 * ASTR;
        #pragma unroll
        for (int i = 0; i < MT; i++) {
            int idx = tid + (i << 8);
            int r = idx >> 3, c4 = (idx & 7) << 2;
            CP16(s2u(Ab + r * ASTR + c4), Ag + (size_t)r * K + c4);
        }
        #pragma unroll
        for (int i = 0; i < 4; i++) {
            int idx = tid + (i << 8);
            int r = idx >> 3, c4 = (idx & 7) << 2;
            CP16(s2u(Bb + r * ASTR + c4), Wg + (size_t)r * K + c4);
        }
    };

    /* prologue: stages 0..2 in flight */
    load_stage(0, 0); CP_COMMIT();
    load_stage(1, 1); CP_COMMIT();
    load_stage(2, 2); CP_COMMIT();

    for (int kt = 0; kt < KT; kt++) {
        int s = kt & (NSTG - 1);
        CP_WAIT(2);            /* stage kt complete (3 pending -> 2) */
        __syncthreads();       /* all threads done with stage (kt-1)%4 too */
        if (kt + 3 < KT) load_stage(kt + 3, (kt + 3) & (NSTG - 1));
        CP_COMMIT();           /* always commit: keeps group accounting fixed */

        const float* Ab = smem + s * STGF + (wm * 32 + r0) * ASTR + k4;
        const float* Bb = smem + s * STGF + 64 * ASTR + (wn * 32 + r0) * ASTR + k4;
        #pragma unroll
        for (int ks = 0; ks < 4; ks++) {
            int kb = ks << 3;
            float af[MT][4], bf[4][2];
            #pragma unroll
            for (int mt = 0; mt < MT; mt++) {
                af[mt][0] = Ab[(mt * 16    ) * ASTR + kb];
                af[mt][1] = Ab[(mt * 16 + 8) * ASTR + kb];
                af[mt][2] = Ab[(mt * 16    ) * ASTR + kb + 4];
                af[mt][3] = Ab[(mt * 16 + 8) * ASTR + kb + 4];
            }
            #pragma unroll
            for (int nt = 0; nt < 4; nt++) {
                bf[nt][0] = Bb[nt * 8 * ASTR + kb];
                bf[nt][1] = Bb[nt * 8 * ASTR + kb + 4];
            }
            #pragma unroll
            for (int mt = 0; mt < MT; mt++)
                #pragma unroll
                for (int nt = 0; nt < 4; nt++)
                    MMA_TF32(acc[mt][nt], af[mt], bf[nt]);
        }
    }

    #pragma unroll
    for (int mt = 0; mt < MT; mt++) {
        int mg = m0 + wm * 32 + mt * 16 + r0;
        #pragma unroll
        for (int nt = 0; nt < 4; nt++) {
            int ng = n0 + wn * 32 + nt * 8 + (k4 << 1);
            float b0 = bias[ng], b1 = bias[ng + 1];
            float* c0p = C + (size_t)mg * N + ng;
            float* c1p = C + (size_t)(mg + 8) * N + ng;
            float o0 = acc[mt][nt][0] + b0, o1 = acc[mt][nt][1] + b1;
            float o2 = acc[mt][nt][2] + b0, o3 = acc[mt][nt][3] + b1;
            if (RELU) {
                o0 = fmaxf(o0, 0.f); o1 = fmaxf(o1, 0.f);
                o2 = fmaxf(o2, 0.f); o3 = fmaxf(o3, 0.f);
            }
            if (ADDC) {
                float2 e0 = *(const float2*)c0p;
                float2 e1 = *(const float2*)c1p;
                o0 += e0.x; o1 += e0.y; o2 += e1.x; o3 += e1.y;
            }
            if (RND) { o0 = rtf32(o0); o1 = rtf32(o1); o2 = rtf32(o2); o3 = rtf32(o3); }
            *(float2*)c0p = make_float2(o0, o1);
            *(float2*)c1p = make_float2(o2, o3);
            if (RC) {
                float* a0p = Caux + (size_t)mg * N + ng;
                float* a1p = Caux + (size_t)(mg + 8) * N + ng;
                *(float2*)a0p = make_float2(rtf32(o0), rtf32(o1));
                *(float2*)a1p = make_float2(rtf32(o2), rtf32(o3));
            }
        }
    }
}

template<int RELU, int ADDC, int RND, int RC>
__global__ __launch_bounds__(256, 2) void mma_gemm(const float* __restrict__ A,
                                                   const float* __restrict__ W,
                                                   const float* __restrict__ bias,
                                                   float* __restrict__ C,
                                                   float* __restrict__ Caux,
                                                   int M, int N, int K) {
    gemm_body<RELU, ADDC, RND, RC>(A, W, bias, C, Caux, M, N, K);
}

__global__ __launch_bounds__(256, 2) void mma_gemm_dual(const float* __restrict__ A0,
                                                        const float* __restrict__ W0,
                                                        const float* __restrict__ b0,
                                                        float* __restrict__ C0,
                                                        const float* __restrict__ A1,
                                                        const float* __restrict__ W1,
                                                        const float* __restrict__ b1,
                                                        float* __restrict__ C1,
                                                        int M, int N, int K) {
    if (blockIdx.z == 0) gemm_body<0, 0, 0, 0>(A0, W0, b0, C0, nullptr, M, N, K);
    else                 gemm_body<0, 0, 0, 0>(A1, W1, b1, C1, nullptr, M, N, K);
}

/* ------- slot init: slots + rounded copy; zero bias buffer ------- */
__global__ void init_slots(const float* __restrict__ noise,
                           const float* __restrict__ mu,
                           const float* __restrict__ logsigma,
                           float* __restrict__ slots,
                           float* __restrict__ srd,
                           float* __restrict__ zero) {
    int idx = blockIdx.x * blockDim.x + threadIdx.x;
    int d = idx & (DIM - 1);
    float v = mu[d] + expf(logsigma[d]) * noise[idx];
    slots[idx] = v;
    srd[idx] = rtf32(v);
    if (idx < DIM) zero[idx] = 0.f;
}

/* ---- merged round-copy of all 4 plain weights ---- */
__global__ void rc_all(const float* __restrict__ Wih, const float* __restrict__ Whh,
                       const float* __restrict__ W1,  const float* __restrict__ W2,
                       float* __restrict__ Wihr, float* __restrict__ Whhr,
                       float* __restrict__ W1r,  float* __restrict__ W2r) {
    int i = blockIdx.x * 256 + threadIdx.x;
    const float* s; float* d; int off;
    if (i < 786432)        { s = Wih; d = Wihr; off = i; }
    else if (i < 1572864)  { s = Whh; d = Whhr; off = i - 786432; }
    else if (i < 1835008)  { s = W1;  d = W1r;  off = i - 1572864; }
    else                   { s = W2;  d = W2r;  off = i - 1835008; }
    d[off] = rtf32(s[off]);
}

/* ---- merged transposed round-copy (z selects Wk/Wq/Wv) ---- */
__global__ void rct_all(const float* __restrict__ Wk, const float* __restrict__ Wq,
                        const float* __restrict__ Wv,
                        float* __restrict__ WkT, float* __restrict__ WqT,
                        float* __restrict__ WvT) {
    __shared__ float tile[32][33];
    const float* src = (blockIdx.z == 0) ? Wk : (blockIdx.z == 1) ? Wq : Wv;
    float* dst       = (blockIdx.z == 0) ? WkT : (blockIdx.z == 1) ? WqT : WvT;
    int c0 = blockIdx.x * 32, d0 = blockIdx.y * 32;
    int tx = threadIdx.x & 31, ty = threadIdx.x >> 5;
    #pragma unroll
    for (int i = 0; i < 32; i += 8)
        tile[ty + i][tx] = src[(size_t)(d0 + ty + i) * DIM + c0 + tx];
    __syncthreads();
    #pragma unroll
    for (int i = 0; i < 32; i += 8)
        dst[(size_t)(c0 + ty + i) * DIM + d0 + tx] = rtf32(tile[tx][ty + i]);
}

/* ---- vec_fold: v = bq@Wk, u = bk@Wq, bc = bv@W_ih^T + b_ih, c0 = bq·bk ---- */
__global__ __launch_bounds__(256) void vec_fold(const float* __restrict__ WkT,
                                                const float* __restrict__ WqT,
                                                const float* __restrict__ W_ih,
                                                const float* __restrict__ bq,
                                                const float* __restrict__ bk,
                                                const float* __restrict__ bv,
                                                const float* __restrict__ b_ih,
                                                float* __restrict__ v,
                                                float* __restrict__ u,
                                                float* __restrict__ bc,
                                                float* __restrict__ c0) {
    int gw = blockIdx.x * 8 + (threadIdx.x >> 5);
    int l = threadIdx.x & 31;
    if (gw >= 2561) return;
    const float* row; const float* vec;
    if (gw < 512)       { row = WkT + (size_t)gw * DIM;          vec = bq; }
    else if (gw < 1024) { row = WqT + (size_t)(gw - 512) * DIM;  vec = bk; }
    else if (gw < 2560) { row = W_ih + (size_t)(gw - 1024) * DIM; vec = bv; }
    else                { row = bq;                               vec = bk; }
    float s = 0.f;
    for (int c = l; c < DIM; c += 32) s += row[c] * vec[c];
    #pragma unroll
    for (int o = 16; o > 0; o >>= 1) s += __shfl_down_sync(0xffffffffu, s, o);
    if (l == 0) {
        if (gw < 512) v[gw] = s;
        else if (gw < 1024) u[gw - 512] = s;
        else if (gw < 2560) bc[gw - 1024] = s + b_ih[gw - 1024];
        else c0[0] = s;
    }
}

/* ---- input LayerNorm: writes bf16 xn (attention-only consumer) ---- */
__global__ void ln_rows_bf(const float* __restrict__ in, __nv_bfloat16* __restrict__ out,
                           const float* __restrict__ gamma, const float* __restrict__ beta) {
    int row = blockIdx.x;
    int t = threadIdx.x;
    const float4* ip = (const float4*)(in + (size_t)row * DIM);
    float4 x = ip[t];
    float s  = x.x + x.y + x.z + x.w;
    float ss = x.x*x.x + x.y*x.y + x.z*x.z + x.w*x.w;
    #pragma unroll
    for (int o = 16; o > 0; o >>= 1) {
        s  += __shfl_down_sync(0xffffffffu, s,  o);
        ss += __shfl_down_sync(0xffffffffu, ss, o);
    }
    __shared__ float sh[8];
    int w = t >> 5, l = t & 31;
    if (l == 0) { sh[w] = s; sh[4 + w] = ss; }
    __syncthreads();
    s  = sh[0] + sh[1] + sh[2] + sh[3];
    ss = sh[4] + sh[5] + sh[6] + sh[7];
    float mean = s * (1.0f / DIM);
    float var  = ss * (1.0f / DIM) - mean * mean;
    float rstd = rsqrtf(var + LN_EPS);
    float4 g = ((const float4*)gamma)[t];
    float4 b = ((const float4*)beta)[t];
    __nv_bfloat162 h0 = __floats2bfloat162_rn((x.x - mean) * rstd * g.x + b.x,
                                              (x.y - mean) * rstd * g.y + b.y);
    __nv_bfloat162 h1 = __floats2bfloat162_rn((x.z - mean) * rstd * g.z + b.z,
                                              (x.w - mean) * rstd * g.w + b.w);
    uint2 pk;
    pk.x = *(uint32_t*)&h0;
    pk.y = *(uint32_t*)&h1;
    *(uint2*)(out + (size_t)row * DIM + 4 * t) = pk;
}

/* ---- slot LayerNorm + fused qbk = out·u + c0 (fp32, feeds GEMM) ---- */
__global__ void ln_rows_q(const float* __restrict__ in, float* __restrict__ out,
                          const float* __restrict__ gamma, const float* __restrict__ beta,
                          const float* __restrict__ u, const float* __restrict__ c0,
                          float* __restrict__ qbk) {
    int row = blockIdx.x;
    int t = threadIdx.x;
    const float4* ip = (const float4*)(in + (size_t)row * DIM);
    float4 x = ip[t];
    float s  = x.x + x.y + x.z + x.w;
    float ss = x.x*x.x + x.y*x.y + x.z*x.z + x.w*x.w;
    #pragma unroll
    for (int o = 16; o > 0; o >>= 1) {
        s  += __shfl_down_sync(0xffffffffu, s,  o);
        ss += __shfl_down_sync(0xffffffffu, ss, o);
    }
    __shared__ float sh[8];
    __shared__ float sh2[4];
    int w = t >> 5, l = t & 31;
    if (l == 0) { sh[w] = s; sh[4 + w] = ss; }
    __syncthreads();
    s  = sh[0] + sh[1] + sh[2] + sh[3];
    ss = sh[4] + sh[5] + sh[6] + sh[7];
    float mean = s * (1.0f / DIM);
    float var  = ss * (1.0f / DIM) - mean * mean;
    float rstd = rsqrtf(var + LN_EPS);
    float4 g = ((const float4*)gamma)[t];
    float4 b = ((const float4*)beta)[t];
    float4 o4;
    o4.x = rtf32((x.x - mean) * rstd * g.x + b.x);
    o4.y = rtf32((x.y - mean) * rstd * g.y + b.y);
    o4.z = rtf32((x.z - mean) * rstd * g.z + b.z);
    o4.w = rtf32((x.w - mean) * rstd * g.w + b.w);
    ((float4*)(out + (size_t)row * DIM))[t] = o4;
    float4 uv = ((const float4*)u)[t];
    float sv = o4.x*uv.x + o4.y*uv.y + o4.z*uv.z + o4.w*uv.w;
    #pragma unroll
    for (int o = 16; o > 0; o >>= 1) sv += __shfl_down_sync(0xffffffffu, sv, o);
    if (l == 0) sh2[w] = sv;
    __syncthreads();
    if (t == 0) qbk[row] = sh2[0] + sh2[1] + sh2[2] + sh2[3] + c0[0];
}

/* ==== fused attention (bf16 xn): dots + softmax + partial V-contraction ==== */
#define KSTR 36
__global__ __launch_bounds__(128) void attn_fused(const __nv_bfloat16* __restrict__ xn,
                                                  const float* __restrict__ qkmat,
                                                  const float* __restrict__ qbk,
                                                  float* __restrict__ paw,
                                                  float* __restrict__ prs) {
    int b = blockIdx.y, blk = blockIdx.x;
    int j0 = blk * 128;
    int tid = threadIdx.x;
    __shared__ __align__(16) float qs[NS][DIM];      /* 16 KB */
    __shared__ __align__(16) float kch[128][KSTR];   /* 18 KB */
    __shared__ __align__(16) float as_t[128][12];    /* 6 KB */
    __shared__ float qb[NS];
    __shared__ float rsm[NS][4];

    {
        const float4* qsrc = (const float4*)(qkmat + (size_t)b * NS * DIM);
        for (int idx = tid; idx < NS * DIM / 4; idx += 128) {
            float4 vv = qsrc[idx];
            int i = idx >> 7, d4 = idx & 127;
            qs[i][d4*4+0] = vv.x; qs[i][d4*4+1] = vv.y;
            qs[i][d4*4+2] = vv.z; qs[i][d4*4+3] = vv.w;
        }
        if (tid < NS) qb[tid] = qbk[b * NS + tid];
    }

    float acc[NS];
    const __nv_bfloat16* kbase = xn + (size_t)(b * NTOK + j0) * DIM;

    /* stage 1: dots; staging converts bf16 -> fp32 in kch */
    for (int dc = 0; dc < DIM; dc += 32) {
        __syncthreads();
        #pragma unroll
        for (int ii = 0; ii < 4; ii++) {
            int idx = tid + ii * 128;
            int r = idx >> 2, cseg = idx & 3;
            uint4 raw = *(const uint4*)(kbase + (size_t)r * DIM + dc + cseg * 8);
            const __nv_bfloat162* hp = (const __nv_bfloat162*)&raw;
            float2 f0 = __bfloat1622float2(hp[0]);
            float2 f1 = __bfloat1622float2(hp[1]);
            float2 f2 = __bfloat1622float2(hp[2]);
            float2 f3 = __bfloat1622float2(hp[3]);
            float4* kp = (float4*)&kch[r][cseg * 8];
            kp[0] = make_float4(f0.x, f0.y, f1.x, f1.y);
            kp[1] = make_float4(f2.x, f2.y, f3.x, f3.y);
        }
        __syncthreads();
        if (dc == 0) {
            #pragma unroll
            for (int i = 0; i < NS; i++) acc[i] = qb[i];
        }
        #pragma unroll
        for (int c4 = 0; c4 < 8; c4++) {
            float4 k4 = *(const float4*)&kch[tid][c4 * 4];
            #pragma unroll
            for (int i = 0; i < NS; i++) {
                float4 q4 = *(const float4*)&qs[i][dc + c4 * 4];
                acc[i] += k4.x*q4.x + k4.y*q4.y + k4.z*q4.z + k4.w*q4.w;
            }
        }
    }

    /* stage 2: softmax over slots; transposed attn + rowsum partials */
    float m = -1e30f;
    #pragma unroll
    for (int i = 0; i < NS; i++) { acc[i] *= ATT_SCALE; m = fmaxf(m, acc[i]); }
    float sum = 0.f;
    #pragma unroll
    for (int i = 0; i < NS; i++) { acc[i] = expf(acc[i] - m); sum += acc[i]; }
    float inv = 1.0f / sum;
    int w = tid >> 5, l = tid & 31;
    #pragma unroll
    for (int i = 0; i < NS; i++) {
        float p = acc[i] * inv + ATT_EPS;
        as_t[tid][i] = p;
        float s = p;
        #pragma unroll
        for (int o = 16; o > 0; o >>= 1) s += __shfl_down_sync(0xffffffffu, s, o);
        if (l == 0) rsm[i][w] = s;
    }
    __syncthreads();
    if (tid < NS)
        prs[((size_t)b * 8 + blk) * NS + tid] = rsm[tid][0] + rsm[tid][1] + rsm[tid][2] + rsm[tid][3];

    /* stage 3: warp w -> cols 128w+4l..+3; bf16 LDG.64 (L2-hot), attn broadcast */
    float4 av[NS];
    #pragma unroll
    for (int i = 0; i < NS; i++) av[i] = make_float4(0.f, 0.f, 0.f, 0.f);
    const __nv_bfloat16* xrow = kbase + w * 128 + l * 4;
    #pragma unroll 4
    for (int j = 0; j < 128; j++) {
        uint2 raw = *(const uint2*)(xrow + (size_t)j * DIM);
        const __nv_bfloat162* hp = (const __nv_bfloat162*)&raw;
        float2 f0 = __bfloat1622float2(hp[0]);
        float2 f1 = __bfloat1622float2(hp[1]);
        float4 xv = make_float4(f0.x, f0.y, f1.x, f1.y);
        float4 a03 = *(const float4*)&as_t[j][0];
        float4 a47 = *(const float4*)&as_t[j][4];
        av[0].x += a03.x*xv.x; av[0].y += a03.x*xv.y; av[0].z += a03.x*xv.z; av[0].w += a03.x*xv.w;
        av[1].x += a03.y*xv.x; av[1].y += a03.y*xv.y; av[1].z += a03.y*xv.z; av[1].w += a03.y*xv.w;
        av[2].x += a03.z*xv.x; av[2].y += a03.z*xv.y; av[2].z += a03.z*xv.z; av[2].w += a03.z*xv.w;
        av[3].x += a03.w*xv.x; av[3].y += a03.w*xv.y; av[3].z += a03.w*xv.z; av[3].w += a03.w*xv.w;
        av[4].x += a47.x*xv.x; av[4].y += a47.x*xv.y; av[4].z += a47.x*xv.z; av[4].w += a47.x*xv.w;
        av[5].x += a47.y*xv.x; av[5].y += a47.y*xv.y; av[5].z += a47.y*xv.z; av[5].w += a47.y*xv.w;
        av[6].x += a47.z*xv.x; av[6].y += a47.z*xv.y; av[6].z += a47.z*xv.z; av[6].w += a47.z*xv.w;
        av[7].x += a47.w*xv.x; av[7].y += a47.w*xv.y; av[7].z += a47.w*xv.z; av[7].w += a47.w*xv.w;
    }
    int c = w * 128 + l * 4;
    #pragma unroll
    for (int i = 0; i < NS; i++)
        *(float4*)(paw + (((size_t)b * 8 + blk) * NS + i) * DIM + c) = av[i];
}

/* ---- reduce partials: awn[b,i,c] = rtf32( sum_blk paw / sum_blk prs ) ---- */
__global__ __launch_bounds__(512) void attn_reduce(const float* __restrict__ paw,
                                                   const float* __restrict__ prs,
                                                   float* __restrict__ awn) {
    int b = blockIdx.x;
    int c = threadIdx.x;
    __shared__ float rs[NS];
    if (c < NS) {
        float s = 0.f;
        #pragma unroll
        for (int blk = 0; blk < 8; blk++)
            s += prs[((size_t)b * 8 + blk) * NS + c];
        rs[c] = 1.0f / s;
    }
    __syncthreads();
    #pragma unroll
    for (int i = 0; i < NS; i++) {
        float s = 0.f;
        #pragma unroll
        for (int blk = 0; blk < 8; blk++)
            s += paw[(((size_t)b * 8 + blk) * NS + i) * DIM + c];
        awn[((size_t)b * NS + i) * DIM + c] = rtf32(s * rs[i]);
    }
}

/* ---- fused GRU gate + LayerNorm(ff) ---- */
__global__ __launch_bounds__(512) void gru_ln(const float* __restrict__ xg,
                                              const float* __restrict__ hg,
                                              float* __restrict__ slots,
                                              float* __restrict__ sbuf,
                                              const float* __restrict__ gamma,
                                              const float* __restrict__ beta) {
    int row = blockIdx.x;
    int c = threadIdx.x;
    size_t base = (size_t)row * 3 * DIM;
    float xr = xg[base + c],         hr = hg[base + c];
    float xz = xg[base + DIM + c],   hz = hg[base + DIM + c];
    float xn = xg[base + 2*DIM + c], hn = hg[base + 2*DIM + c];
    float r = 1.0f / (1.0f + expf(-(xr + hr)));
    float z = 1.0f / (1.0f + expf(-(xz + hz)));
    float n = tanhf(xn + r * hn);
    size_t si = (size_t)row * DIM + c;
    float prev = slots[si];
    float v = (1.0f - z) * n + z * prev;
    slots[si] = v;

    __shared__ float sh[32];
    float s = v, ss = v * v;
    #pragma unroll
    for (int o = 16; o > 0; o >>= 1) {
        s  += __shfl_down_sync(0xffffffffu, s,  o);
        ss += __shfl_down_sync(0xffffffffu, ss, o);
    }
    int w = c >> 5, l = c & 31;
    if (l == 0) { sh[w] = s; sh[16 + w] = ss; }
    __syncthreads();
    float ts = 0.f, tss = 0.f;
    #pragma unroll
    for (int i = 0; i < 16; i++) { ts += sh[i]; tss += sh[16 + i]; }
    float mean = ts * (1.0f / DIM);
    float var  = tss * (1.0f / DIM) - mean * mean;
    float rstd = rsqrtf(var + LN_EPS);
    sbuf[si] = rtf32((v - mean) * rstd * gamma[c] + beta[c]);
}

/* ---------------- host ---------------- */
static void* symv(const void* s) {
    void* p = nullptr;
    cudaGetSymbolAddress(&p, s);
    return p;
}

extern "C" void kernel_launch(void* const* d_in, const int* in_sizes, int n_in,
                              void* d_out, int out_size) {
    const float* inputs    = (const float*)d_in[0];
    const float* noise     = (const float*)d_in[1];
    const float* mu        = (const float*)d_in[2];
    const float* logsigma  = (const float*)d_in[3];
    const float* gi        = (const float*)d_in[4];
    const float* bei       = (const float*)d_in[5];
    const float* gsl       = (const float*)d_in[6];
    const float* besl      = (const float*)d_in[7];
    const float* gff       = (const float*)d_in[8];
    const float* beff      = (const float*)d_in[9];
    const float* Wq        = (const float*)d_in[10];
    const float* bq        = (const float*)d_in[11];
    const float* Wk        = (const float*)d_in[12];
    const float* bk        = (const float*)d_in[13];
    const float* Wv        = (const float*)d_in[14];
    const float* bv        = (const float*)d_in[15];
    const float* W_ih      = (const float*)d_in[16];
    const float* b_ih      = (const float*)d_in[17];
    const float* W_hh      = (const float*)d_in[18];
    const float* b_hh      = (const float*)d_in[19];
    const float* W1        = (const float*)d_in[20];
    const float* b1        = (const float*)d_in[21];
    const float* W2        = (const float*)d_in[22];
    const float* b2        = (const float*)d_in[23];
    float* slots = (float*)d_out;

    __nv_bfloat16* xn = (__nv_bfloat16*)symv(g_xn);
    float* WkT  = (float*)symv(g_WkT);
    float* WqT  = (float*)symv(g_WqT);
    float* WvT  = (float*)symv(g_WvT);
    float* Wp   = (float*)symv(g_Wp);
    float* Wc   = (float*)symv(g_Wc);
    float* Wihr = (float*)symv(g_Wih_r);
    float* Whhr = (float*)symv(g_Whh_r);
    float* W1r  = (float*)symv(g_W1_r);
    float* W2r  = (float*)symv(g_W2_r);
    float* zero = (float*)symv(g_zero);
    float* vv   = (float*)symv(g_v);
    float* uu   = (float*)symv(g_u);
    float* c0   = (float*)symv(g_c0);
    float* bc   = (float*)symv(g_bc);
    float* sbuf = (float*)symv(g_s);
    float* srd  = (float*)symv(g_sr);
    float* qk   = (float*)symv(g_qk);
    float* qbk  = (float*)symv(g_qbk);
    float* paw  = (float*)symv(g_paw);
    float* prs  = (float*)symv(g_prs);
    float* awn  = (float*)symv(g_awn);
    float* xg   = (float*)symv(g_xg);
    float* hg   = (float*)symv(g_hg);
    float* hid  = (float*)symv(g_hid);

    cudaFuncSetAttribute(mma_gemm<0,0,0,0>, cudaFuncAttributeMaxDynamicSharedMemorySize, GSMEM);
    cudaFuncSetAttribute(mma_gemm<0,0,1,0>, cudaFuncAttributeMaxDynamicSharedMemorySize, GSMEM);
    cudaFuncSetAttribute(mma_gemm<1,0,1,0>, cudaFuncAttributeMaxDynamicSharedMemorySize, GSMEM);
    cudaFuncSetAttribute(mma_gemm<0,1,0,1>, cudaFuncAttributeMaxDynamicSharedMemorySize, GSMEM);
    cudaFuncSetAttribute(mma_gemm_dual,     cudaFuncAttributeMaxDynamicSharedMemorySize, GSMEM);

    /* ln_rows_bf(inputs) is my launch #4 (ncu -s 5 -c 1 captures it) */
    init_slots<<<SROWS*DIM/256, 256>>>(noise, mu, logsigma, slots, srd, zero); /* 1 */
    rct_all<<<dim3(16,16,3), 256>>>(Wk, Wq, Wv, WkT, WqT, WvT);                /* 2 */
    rc_all<<<2097152/256, 256>>>(W_ih, W_hh, W1, W2, Wihr, Whhr, W1r, W2r);    /* 3 */
    ln_rows_bf<<<NROWS, 128>>>(inputs, xn, gi, bei);                           /* 4 */
    mma_gemm<0,0,1,0><<<dim3(DIM/128, DIM/64), 256, GSMEM>>>(WkT, WqT, zero, Wp, nullptr, DIM, DIM, DIM);
    mma_gemm<0,0,1,0><<<dim3(DIM/128, 3*DIM/64), 256, GSMEM>>>(Wihr, WvT, zero, Wc, nullptr, 3*DIM, DIM, DIM);
    vec_fold<<<321, 256>>>(WkT, WqT, W_ih, bq, bk, bv, b_ih, vv, uu, bc, c0);

    for (int it = 0; it < 3; it++) {
        ln_rows_q<<<SROWS, 128>>>(slots, sbuf, gsl, besl, uu, c0, qbk);
        mma_gemm<0,0,0,0><<<dim3(DIM/128, SROWS/64), 256, GSMEM>>>(sbuf, Wp, vv, qk, nullptr, SROWS, DIM, DIM);
        attn_fused<<<dim3(8, BATCH), 128>>>(xn, qk, qbk, paw, prs);
        attn_reduce<<<BATCH, 512>>>(paw, prs, awn);
        mma_gemm_dual<<<dim3(3*DIM/128, SROWS/64, 2), 256, GSMEM>>>(
            awn, Wc, bc, xg, srd, Whhr, b_hh, hg, SROWS, 3*DIM, DIM);
        gru_ln<<<SROWS, 512>>>(xg, hg, slots, sbuf, gff, beff);
        mma_gemm<1,0,1,0><<<dim3(HIDN/128, SROWS/64), 256, GSMEM>>>(sbuf, W1r, b1, hid, nullptr, SROWS, HIDN, DIM);
        mma_gemm<0,1,0,1><<<dim3(DIM/128, SROWS/64), 256, GSMEM>>>(hid, W2r, b2, slots, srd, SROWS, DIM, HIDN);
    }
    (void)in_sizes; (void)n_in; (void)out_size;
}